// round 3
// baseline (speedup 1.0000x reference)
#include <cuda_runtime.h>
#include <cuda_bf16.h>
#include <cstdint>

#define EPS 1e-9f
#define BATCH 128
#define NN 400
#define HH 128
#define NSQ (NN * NN)
#define KTOP 32000

// ---------------- scratch ----------------------------------------------------
__device__ float g_xf[BATCH * NSQ];
__device__ float g_delta[BATCH * NSQ];
__device__ float g_out1[BATCH * HH * NN];
__device__ float g_out2a[BATCH * HH * HH];
__device__ float g_out2[BATCH * HH * NN];
__device__ float g_h1[BATCH * NN * HH];
__device__ unsigned long long g_thresh[BATCH];
__device__ float g_dinv[BATCH * NN];
__device__ float g_rs[BATCH * NN];

// ---------------- fisher -----------------------------------------------------
__global__ void fisher_k(const float* __restrict__ x, float* __restrict__ xf) {
    int r = blockIdx.x * 256 + threadIdx.x;
    int b = blockIdx.y;
    size_t base = (size_t)b * NSQ;
    float x00 = x[base];
    float d = 0.5f * logf((1.f + x00 + EPS) / (1.f - x00 + EPS));
    float v = x[base + r];
    float f = 0.5f * logf((1.f + v + EPS) / (1.f - v + EPS));
    xf[base + r] = f / d;
}

// ---------------- symmetrize -------------------------------------------------
__global__ void sym_k(float* __restrict__ xf, const float* __restrict__ delta) {
    int b = blockIdx.z;
    int j0 = blockIdx.x * 32, i0 = blockIdx.y * 32;
    int tx = threadIdx.x, ty = threadIdx.y;
    __shared__ float sh[32][33];
    size_t base = (size_t)b * NSQ;
    int lr = j0 + ty, lc = i0 + tx;
    sh[ty][tx] = (lr < NN && lc < NN) ? delta[base + (size_t)lr * NN + lc] : 0.f;
    __syncthreads();
    int i = i0 + ty, j = j0 + tx;
    if (i < NN && j < NN) {
        size_t idx = base + (size_t)i * NN + j;
        float v = xf[idx];
        if (i != j) v += 0.5f * (delta[idx] + sh[tx][ty]);
        xf[idx] = v;
    }
}

// ---------------- exact top-k threshold --------------------------------------
__device__ __forceinline__ unsigned long long make_key(float v, unsigned t) {
    unsigned u = __float_as_uint(v);
    unsigned k32 = (u & 0x80000000u) ? ~u : (u | 0x80000000u);
    return ((unsigned long long)k32 << 32) | (unsigned long long)(~t);
}

__global__ void radix_select_k(const float* __restrict__ x2,
                               unsigned long long* __restrict__ thresh) {
    const int b = blockIdx.x;
    const float* xp = x2 + (size_t)b * NSQ;
    __shared__ unsigned hist[16][256];
    __shared__ unsigned total[256];
    __shared__ unsigned long long s_prefix;
    __shared__ unsigned s_remaining;
    int tid = threadIdx.x;
    int wid = tid >> 5, lane = tid & 31;
    if (tid == 0) { s_prefix = 0ull; s_remaining = KTOP; }
    __syncthreads();
    for (int pass = 0; pass < 8; pass++) {
        int shift = 56 - 8 * pass;
        for (int i = tid; i < 16 * 256; i += 512) ((unsigned*)hist)[i] = 0;
        __syncthreads();
        unsigned long long prefix = s_prefix;
        int hs = shift + 8;
        for (int t = tid; t < 160256; t += 512) {
            bool inr = t < NSQ;
            unsigned long long key = inr ? make_key(xp[t], (unsigned)t) : 0ull;
            bool ok = inr && ((hs >= 64) || ((key >> hs) == (prefix >> hs)));
            unsigned bin = (unsigned)((key >> shift) & 255);
            unsigned active = __ballot_sync(0xffffffffu, ok);
            if (ok) {
                unsigned peers = __match_any_sync(active, bin);
                int leader = __ffs(peers) - 1;
                if (lane == leader) atomicAdd(&hist[wid][bin], __popc(peers));
            }
        }
        __syncthreads();
        for (int i = tid; i < 256; i += 512) {
            unsigned s = 0;
            #pragma unroll
            for (int w = 0; w < 16; w++) s += hist[w][i];
            total[i] = s;
        }
        __syncthreads();
        if (tid == 0) {
            unsigned rem = s_remaining, cum = 0;
            int chosen = 0;
            for (int bin = 255; bin >= 0; bin--) {
                unsigned c = total[bin];
                if (cum + c >= rem) { chosen = bin; s_remaining = rem - cum; break; }
                cum += c;
            }
            s_prefix |= ((unsigned long long)chosen << shift);
        }
        __syncthreads();
    }
    if (tid == 0) thresh[b] = s_prefix;
}

// ---------------- mask / deg / An --------------------------------------------
__global__ void mask_k(const float* __restrict__ x2,
                       const unsigned long long* __restrict__ thresh,
                       float* __restrict__ A) {
    int r = blockIdx.x * 256 + threadIdx.x;
    int b = blockIdx.y;
    size_t idx = (size_t)b * NSQ + r;
    float v = x2[idx];
    unsigned long long key = make_key(v, (unsigned)r);
    float a = (key >= thresh[b]) ? v : 0.f;
    int i = r / NN, j = r - i * NN;
    if (i == j && a == 0.f) a = 1.f;
    A[idx] = a;
}

__global__ void deg_k(const float* __restrict__ A, float* __restrict__ dinv) {
    int b = blockIdx.x;
    int j = threadIdx.x;
    if (j >= NN) return;
    const float* Ab = A + (size_t)b * NSQ;
    float acc = 0.f;
    #pragma unroll 4
    for (int i = 0; i < NN; i++) acc += Ab[(size_t)i * NN + j];
    float dv = rsqrtf(acc);
    if (isinf(dv)) dv = 0.f;
    dinv[b * NN + j] = dv;
}

__global__ void an_k(float* __restrict__ A, const float* __restrict__ dinv,
                     float* __restrict__ rs) {
    int i = blockIdx.x, b = blockIdx.y;
    int tid = threadIdx.x;
    const float* dv = dinv + b * NN;
    float* row = A + (size_t)b * NSQ + (size_t)i * NN;
    float di = dv[i];
    float acc = 0.f;
    for (int j = tid; j < NN; j += 128) {
        float v = row[j] * di * dv[j];
        row[j] = v;
        acc += v;
    }
    __shared__ float sb[128];
    sb[tid] = acc;
    __syncthreads();
    for (int s = 64; s > 0; s >>= 1) {
        if (tid < s) sb[tid] += sb[tid + s];
        __syncthreads();
    }
    if (tid == 0) rs[b * NN + i] = sb[0] * (1.f / NN);
}

// ================= bf16 split tensor-core GEMM ================================
// C[M,N] = A @ B (+bias)(+skip)(relu), via hi/lo bf16 split, f32 accumulate.
// A: TRANSA=0 -> gmem [M][lda]; TRANSA=1 -> gmem [K][lda] (lda = m-stride)
// B: gmem [K][ldb] row-major (K-major for N)
#define BM 128
#define BN 64
#define BK 16
#define BKP 24   // padded row (bf16 units): +16B => conflict-free ldmatrix

__device__ __forceinline__ void ldm_x4(uint32_t* r, uint32_t a) {
    asm volatile("ldmatrix.sync.aligned.m8n8.x4.shared.b16 {%0,%1,%2,%3}, [%4];"
        : "=r"(r[0]), "=r"(r[1]), "=r"(r[2]), "=r"(r[3]) : "r"(a));
}
__device__ __forceinline__ void ldm_x2(uint32_t* r, uint32_t a) {
    asm volatile("ldmatrix.sync.aligned.m8n8.x2.shared.b16 {%0,%1}, [%2];"
        : "=r"(r[0]), "=r"(r[1]) : "r"(a));
}
__device__ __forceinline__ void mma16816(float* d, const uint32_t* a, const uint32_t* b) {
    asm volatile("mma.sync.aligned.m16n8k16.row.col.f32.bf16.bf16.f32 "
        "{%0,%1,%2,%3}, {%4,%5,%6,%7}, {%8,%9}, {%0,%1,%2,%3};"
        : "+f"(d[0]), "+f"(d[1]), "+f"(d[2]), "+f"(d[3])
        : "r"(a[0]), "r"(a[1]), "r"(a[2]), "r"(a[3]), "r"(b[0]), "r"(b[1]));
}
__device__ __forceinline__ void split_store(__nv_bfloat16* ph, __nv_bfloat16* pl, float v) {
    __nv_bfloat16 h = __float2bfloat16(v);
    *ph = h;
    *pl = __float2bfloat16(v - __bfloat162float(h));
}

template<int TRANSA, int EPI, int TRANSOUT>
__global__ void __launch_bounds__(256, 2)
mmagemm_k(const float* __restrict__ A, size_t strideA, int lda,
          const float* __restrict__ Bm, size_t strideB, int ldb,
          const float* __restrict__ bias,
          const float* __restrict__ skip, size_t strideS, int lds,
          float* __restrict__ C, size_t strideC, int ldc,
          int M, int N, int K) {
    int b = blockIdx.z;
    A += (size_t)b * strideA;
    Bm += (size_t)b * strideB;
    if (EPI == 2) skip += (size_t)b * strideS;
    C += (size_t)b * strideC;

    int n0 = blockIdx.x * BN;
    int m0 = blockIdx.y * BM;

    __shared__ __nv_bfloat16 sA[2][BM][BKP];
    __shared__ __nv_bfloat16 sB[2][BN][BKP];

    int tid = threadIdx.x;          // 256 = 8 warps
    int warp = tid >> 5, lane = tid & 31;
    int wm = (warp >> 1) * 32;      // 4 warps along M
    int wn = (warp & 1) * 32;       // 2 warps along N
    int gid = lane >> 2, tig = lane & 3;

    float acc[2][4][4] = {};

    // precomputed ldmatrix smem addresses (invariant across k-loop)
    uint32_t aAddrH[2], aAddrL[2], bAddrH[4], bAddrL[4];
    {
        int arow = wm + (lane & 15);
        int acol = (lane >> 4) * 8;
        aAddrH[0] = (uint32_t)__cvta_generic_to_shared(&sA[0][arow][acol]);
        aAddrH[1] = (uint32_t)__cvta_generic_to_shared(&sA[0][arow + 16][acol]);
        aAddrL[0] = (uint32_t)__cvta_generic_to_shared(&sA[1][arow][acol]);
        aAddrL[1] = (uint32_t)__cvta_generic_to_shared(&sA[1][arow + 16][acol]);
        int brow = lane & 7;
        int bcol = ((lane >> 3) & 1) * 8;
        #pragma unroll
        for (int ni = 0; ni < 4; ni++) {
            bAddrH[ni] = (uint32_t)__cvta_generic_to_shared(&sB[0][wn + ni * 8 + brow][bcol]);
            bAddrL[ni] = (uint32_t)__cvta_generic_to_shared(&sB[1][wn + ni * 8 + brow][bcol]);
        }
    }

    for (int k0 = 0; k0 < K; k0 += BK) {
        // ---- stage A tile (BM x BK) ----
        if (TRANSA == 0) {
            #pragma unroll
            for (int it = 0; it < 2; it++) {
                int s = tid + it * 256;           // 512 float4 slots
                int row = s >> 2, c4 = (s & 3) * 4;
                int m = m0 + row;
                float4 v = make_float4(0.f, 0.f, 0.f, 0.f);
                if (m < M) v = *(const float4*)&A[(size_t)m * lda + k0 + c4];
                split_store(&sA[0][row][c4 + 0], &sA[1][row][c4 + 0], v.x);
                split_store(&sA[0][row][c4 + 1], &sA[1][row][c4 + 1], v.y);
                split_store(&sA[0][row][c4 + 2], &sA[1][row][c4 + 2], v.z);
                split_store(&sA[0][row][c4 + 3], &sA[1][row][c4 + 3], v.w);
            }
        } else {
            #pragma unroll
            for (int it = 0; it < 2; it++) {
                int s = tid + it * 256;           // 16 k-rows x 32 m-float4
                int kr = s >> 5, mc4 = (s & 31) * 4;
                int m = m0 + mc4;
                float4 v = make_float4(0.f, 0.f, 0.f, 0.f);
                if (m < M) v = *(const float4*)&A[(size_t)(k0 + kr) * lda + m];
                split_store(&sA[0][mc4 + 0][kr], &sA[1][mc4 + 0][kr], v.x);
                split_store(&sA[0][mc4 + 1][kr], &sA[1][mc4 + 1][kr], v.y);
                split_store(&sA[0][mc4 + 2][kr], &sA[1][mc4 + 2][kr], v.z);
                split_store(&sA[0][mc4 + 3][kr], &sA[1][mc4 + 3][kr], v.w);
            }
        }
        // ---- stage B tile (BK x BN) -> smem [n][k] ----
        {
            int kr = tid >> 4, nc4 = (tid & 15) * 4;   // 256 float4 slots
            int n = n0 + nc4;
            float4 v = make_float4(0.f, 0.f, 0.f, 0.f);
            if (n < N) v = *(const float4*)&Bm[(size_t)(k0 + kr) * ldb + n];
            split_store(&sB[0][nc4 + 0][kr], &sB[1][nc4 + 0][kr], v.x);
            split_store(&sB[0][nc4 + 1][kr], &sB[1][nc4 + 1][kr], v.y);
            split_store(&sB[0][nc4 + 2][kr], &sB[1][nc4 + 2][kr], v.z);
            split_store(&sB[0][nc4 + 3][kr], &sB[1][nc4 + 3][kr], v.w);
        }
        __syncthreads();

        uint32_t ah[2][4], al[2][4];
        ldm_x4(ah[0], aAddrH[0]); ldm_x4(ah[1], aAddrH[1]);
        ldm_x4(al[0], aAddrL[0]); ldm_x4(al[1], aAddrL[1]);
        #pragma unroll
        for (int ni = 0; ni < 4; ni++) {
            uint32_t bh[2], bl[2];
            ldm_x2(bh, bAddrH[ni]);
            ldm_x2(bl, bAddrL[ni]);
            #pragma unroll
            for (int mi = 0; mi < 2; mi++) {
                mma16816(acc[mi][ni], ah[mi], bh);
                mma16816(acc[mi][ni], al[mi], bh);
                mma16816(acc[mi][ni], ah[mi], bl);
            }
        }
        __syncthreads();
    }

    // ---- epilogue ----
    #pragma unroll
    for (int mi = 0; mi < 2; mi++) {
        #pragma unroll
        for (int ni = 0; ni < 4; ni++) {
            int cbase = n0 + wn + ni * 8 + 2 * tig;
            #pragma unroll
            for (int h = 0; h < 2; h++) {          // h=0: row gid, h=1: row gid+8
                int m = m0 + wm + mi * 16 + gid + h * 8;
                if (m >= M) continue;
                #pragma unroll
                for (int e = 0; e < 2; e++) {
                    int n = cbase + e;
                    if (n >= N) continue;
                    float v = acc[mi][ni][h * 2 + e];
                    if (bias) v += bias[n];
                    if (EPI == 2) v += skip[(size_t)m * lds + n];
                    if (EPI >= 1) v = fmaxf(v, 0.f);
                    if (TRANSOUT) C[(size_t)n * ldc + m] = v;
                    else          C[(size_t)m * ldc + n] = v;
                }
            }
        }
    }
}

// ---------------- head --------------------------------------------------------
__global__ void head_k(const float* __restrict__ Y2, const float* __restrict__ rs,
                       const float* __restrict__ b2, const float* __restrict__ fcw,
                       const float* __restrict__ fcb, float* __restrict__ out) {
    int b = blockIdx.x;
    int f = threadIdx.x;
    const float* Y = Y2 + (size_t)b * (NN * HH);
    const float* r = rs + b * NN;
    float acc = 0.f;
    for (int i = 0; i < NN; i++) acc += r[i] * Y[(size_t)i * HH + f];
    acc += b2[f];
    float pf = fmaxf(acc, 0.f);
    __shared__ float sp[HH];
    sp[f] = pf;
    __syncthreads();
    if (f < 2) {
        float o = fcb[f];
        for (int q = 0; q < HH; q++) o += sp[q] * fcw[q * 2 + f];
        out[b * 2 + f] = o;
    }
}

// -------------------------------------------------------------------------------
extern "C" void kernel_launch(void* const* d_in, const int* in_sizes, int n_in,
                              void* d_out, int out_size) {
    const float* x      = (const float*)d_in[0];
    const float* enc1_w = (const float*)d_in[2];
    const float* enc1_b = (const float*)d_in[3];
    const float* enc2_w = (const float*)d_in[4];
    const float* enc2_b = (const float*)d_in[5];
    const float* dec2_w = (const float*)d_in[6];
    const float* dec2_b = (const float*)d_in[7];
    const float* dec1_w = (const float*)d_in[8];
    const float* dec1_b = (const float*)d_in[9];
    const float* gcn1_w = (const float*)d_in[10];
    const float* gcn1_b = (const float*)d_in[11];
    const float* gcn2_w = (const float*)d_in[12];
    const float* gcn2_b = (const float*)d_in[13];
    const float* fc_w   = (const float*)d_in[14];
    const float* fc_b   = (const float*)d_in[15];
    float* out = (float*)d_out;

    float *xf, *delta, *out1, *out2a, *out2, *h1, *dinv, *rs;
    unsigned long long* thresh;
    cudaGetSymbolAddress((void**)&xf, g_xf);
    cudaGetSymbolAddress((void**)&delta, g_delta);
    cudaGetSymbolAddress((void**)&out1, g_out1);
    cudaGetSymbolAddress((void**)&out2a, g_out2a);
    cudaGetSymbolAddress((void**)&out2, g_out2);
    cudaGetSymbolAddress((void**)&h1, g_h1);
    cudaGetSymbolAddress((void**)&thresh, g_thresh);
    cudaGetSymbolAddress((void**)&dinv, g_dinv);
    cudaGetSymbolAddress((void**)&rs, g_rs);

    const size_t S_NN = (size_t)NSQ;
    const size_t S_HN = (size_t)HH * NN;
    const size_t S_HH = (size_t)HH * HH;

    // 0) fisher
    fisher_k<<<dim3(625, BATCH), 256>>>(x, xf);

    // 1) out1[b,h,i] = relu(xf @ enc1_w + b), stored transposed [H][N]
    mmagemm_k<0, 1, 1><<<dim3(2, 4, BATCH), 256>>>(
        xf, S_NN, NN, enc1_w, 0, HH, enc1_b, nullptr, 0, 0,
        out1, S_HN, NN, NN, HH, NN);

    // 2) out2a = relu(out1 @ enc2_w + b)   [B,H,H]
    mmagemm_k<0, 1, 0><<<dim3(2, 1, BATCH), 256>>>(
        out1, S_HN, NN, enc2_w, 0, HH, enc2_b, nullptr, 0, 0,
        out2a, S_HH, HH, HH, HH, NN);

    // 3) out2 = relu(out2a @ dec2_w + b + out1)  [B,H,N]
    mmagemm_k<0, 2, 0><<<dim3(7, 1, BATCH), 256>>>(
        out2a, S_HH, HH, dec2_w, 0, NN, dec2_b, out1, S_HN, NN,
        out2, S_HN, NN, HH, NN, HH);

    // 4) delta = out2^T @ dec1_w + b  (A = out2 as gmem [K=128][M=400])
    mmagemm_k<1, 0, 0><<<dim3(7, 4, BATCH), 256>>>(
        out2, S_HN, NN, dec1_w, 0, NN, dec1_b, nullptr, 0, 0,
        delta, S_NN, NN, NN, NN, HH);

    // 5) x2 = xf + 0.5*(delta + delta^T)*(1-eye)
    sym_k<<<dim3(13, 13, BATCH), dim3(32, 32)>>>(xf, delta);

    // 6) exact top-k threshold
    radix_select_k<<<BATCH, 512>>>(xf, thresh);

    // 7) A = masked x2 (+ self loops) -> delta buffer
    mask_k<<<dim3(625, BATCH), 256>>>(xf, thresh, delta);

    // 8) dinv
    deg_k<<<BATCH, 512>>>(delta, dinv);

    // 9) An in place + row means
    an_k<<<dim3(NN, BATCH), 128>>>(delta, dinv, rs);

    // 10) Y1 = x2 @ gcn1_w  [B,N,H] -> out2 buffer
    mmagemm_k<0, 0, 0><<<dim3(2, 4, BATCH), 256>>>(
        xf, S_NN, NN, gcn1_w, 0, HH, nullptr, nullptr, 0, 0,
        out2, S_HN, HH, NN, HH, NN);

    // 11) h1 = relu(An^T @ Y1 + gcn1_b)  (A = An as gmem [K=400][M=400])
    mmagemm_k<1, 1, 0><<<dim3(2, 4, BATCH), 256>>>(
        delta, S_NN, NN, out2, S_HN, HH, gcn1_b, nullptr, 0, 0,
        h1, S_HN, HH, NN, HH, NN);

    // 12) Y2 = h1 @ gcn2_w  -> out1 buffer
    mmagemm_k<0, 0, 0><<<dim3(2, 4, BATCH), 256>>>(
        h1, S_HN, HH, gcn2_w, 0, HH, nullptr, nullptr, 0, 0,
        out1, S_HN, HH, NN, HH, HH);

    // 13) head
    head_k<<<BATCH, HH>>>(out1, rs, gcn2_b, fc_w, fc_b, out);
}

// round 4
// speedup vs baseline: 1.9609x; 1.9609x over previous
#include <cuda_runtime.h>
#include <cuda_bf16.h>
#include <cstdint>

#define EPS 1e-9f
#define BATCH 128
#define NN 400
#define HH 128
#define NSQ (NN * NN)          // 160000
#define S_HN (HH * NN)         // 51200
#define S_HH (HH * HH)         // 16384
#define KTOP 32000

typedef __nv_bfloat16 bf16;

// ---------------- scratch -----------------------------------------------------
__device__ float g_xf[BATCH * NSQ];         // xf then x2 (in place)
__device__ float g_delta[BATCH * NSQ];      // delta then masked A
__device__ float g_out1[BATCH * S_HN];      // out1 fp32 (skip operand)
__device__ float g_y2t[BATCH * S_HN];       // Y2^T fp32
__device__ bf16 g_ah[BATCH * NSQ], g_al[BATCH * NSQ];     // xf then x2 split
__device__ bf16 g_anh[BATCH * NSQ], g_anl[BATCH * NSQ];   // An split
__device__ bf16 g_o1h[BATCH * S_HN], g_o1l[BATCH * S_HN]; // out1 [H][N]
__device__ bf16 g_o2ah[BATCH * S_HH], g_o2al[BATCH * S_HH];
__device__ bf16 g_o2th[BATCH * S_HN], g_o2tl[BATCH * S_HN]; // out2^T [N][H]
__device__ bf16 g_y1h[BATCH * S_HN], g_y1l[BATCH * S_HN];   // Y1^T [H][N]
__device__ bf16 g_h1h[BATCH * S_HN], g_h1l[BATCH * S_HN];   // h1^T [H][N]
__device__ bf16 g_wh[272384], g_wl[272384];  // split weights
__device__ unsigned long long g_thresh[BATCH];
__device__ float g_dinv[BATCH * NN];
__device__ float g_rs[BATCH * NN];

// weight offsets in g_wh/g_wl
#define W_E1 0
#define W_E2 51200
#define W_D2 102400
#define W_D1 153600
#define W_G1 204800
#define W_G2T 256000

__device__ __forceinline__ void fsplit(float v, bf16* h, bf16* l) {
    bf16 hh = __float2bfloat16(v);
    *h = hh;
    *l = __float2bfloat16(v - __bfloat162float(hh));
}

// ---------------- weight prep --------------------------------------------------
__global__ void wsplit_k(const float* __restrict__ w, bf16* __restrict__ h,
                         bf16* __restrict__ l, int n) {
    int i = blockIdx.x * 256 + threadIdx.x;
    if (i < n) fsplit(w[i], &h[i], &l[i]);
}
// gcn2_w [128][128] -> transposed split
__global__ void wtsplit_k(const float* __restrict__ w, bf16* __restrict__ h,
                          bf16* __restrict__ l) {
    int i = blockIdx.x * 256 + threadIdx.x;   // i = g*128 + f
    int g = i >> 7, f = i & 127;
    fsplit(w[f * HH + g], &h[i], &l[i]);
}

// ---------------- fisher + split ------------------------------------------------
__global__ void fisher_k(const float* __restrict__ x, float* __restrict__ xf,
                         bf16* __restrict__ xh, bf16* __restrict__ xl) {
    int r = blockIdx.x * 256 + threadIdx.x;
    int b = blockIdx.y;
    size_t base = (size_t)b * NSQ;
    float x00 = x[base];
    float d = 0.5f * logf((1.f + x00 + EPS) / (1.f - x00 + EPS));
    float v = x[base + r];
    float f = 0.5f * logf((1.f + v + EPS) / (1.f - v + EPS));
    float o = f / d;
    xf[base + r] = o;
    fsplit(o, &xh[base + r], &xl[base + r]);
}

// ---------------- symmetrize + split -------------------------------------------
__global__ void sym_k(float* __restrict__ xf, const float* __restrict__ delta,
                      bf16* __restrict__ xh, bf16* __restrict__ xl) {
    int b = blockIdx.z;
    int j0 = blockIdx.x * 32, i0 = blockIdx.y * 32;
    int tx = threadIdx.x, ty = threadIdx.y;
    __shared__ float sh[32][33];
    size_t base = (size_t)b * NSQ;
    int lr = j0 + ty, lc = i0 + tx;
    sh[ty][tx] = (lr < NN && lc < NN) ? delta[base + (size_t)lr * NN + lc] : 0.f;
    __syncthreads();
    int i = i0 + ty, j = j0 + tx;
    if (i < NN && j < NN) {
        size_t idx = base + (size_t)i * NN + j;
        float v = xf[idx];
        if (i != j) v += 0.5f * (delta[idx] + sh[tx][ty]);
        xf[idx] = v;
        fsplit(v, &xh[idx], &xl[idx]);
    }
}

// ---------------- exact top-k threshold ----------------------------------------
__device__ __forceinline__ unsigned long long make_key(float v, unsigned t) {
    unsigned u = __float_as_uint(v);
    unsigned k32 = (u & 0x80000000u) ? ~u : (u | 0x80000000u);
    return ((unsigned long long)k32 << 32) | (unsigned long long)(~t);
}

__global__ void radix_select_k(const float* __restrict__ x2,
                               unsigned long long* __restrict__ thresh) {
    const int b = blockIdx.x;
    const float* xp = x2 + (size_t)b * NSQ;
    __shared__ unsigned hist[16][256];
    __shared__ unsigned total[256];
    __shared__ unsigned long long s_prefix;
    __shared__ unsigned s_remaining;
    int tid = threadIdx.x;
    int wid = tid >> 5, lane = tid & 31;
    if (tid == 0) { s_prefix = 0ull; s_remaining = KTOP; }
    __syncthreads();
    for (int pass = 0; pass < 8; pass++) {
        int shift = 56 - 8 * pass;
        for (int i = tid; i < 16 * 256; i += 512) ((unsigned*)hist)[i] = 0;
        __syncthreads();
        unsigned long long prefix = s_prefix;
        int hs = shift + 8;
        for (int t = tid; t < 160256; t += 512) {
            bool inr = t < NSQ;
            unsigned long long key = inr ? make_key(xp[t], (unsigned)t) : 0ull;
            bool ok = inr && ((hs >= 64) || ((key >> hs) == (prefix >> hs)));
            unsigned bin = (unsigned)((key >> shift) & 255);
            unsigned active = __ballot_sync(0xffffffffu, ok);
            if (ok) {
                unsigned peers = __match_any_sync(active, bin);
                int leader = __ffs(peers) - 1;
                if (lane == leader) atomicAdd(&hist[wid][bin], __popc(peers));
            }
        }
        __syncthreads();
        for (int i = tid; i < 256; i += 512) {
            unsigned s = 0;
            #pragma unroll
            for (int w = 0; w < 16; w++) s += hist[w][i];
            total[i] = s;
        }
        __syncthreads();
        if (tid == 0) {
            unsigned rem = s_remaining, cum = 0;
            int chosen = 0;
            for (int bin = 255; bin >= 0; bin--) {
                unsigned c = total[bin];
                if (cum + c >= rem) { chosen = bin; s_remaining = rem - cum; break; }
                cum += c;
            }
            s_prefix |= ((unsigned long long)chosen << shift);
        }
        __syncthreads();
    }
    if (tid == 0) thresh[b] = s_prefix;
}

// ---------------- mask / deg / An(split) ---------------------------------------
__global__ void mask_k(const float* __restrict__ x2,
                       const unsigned long long* __restrict__ thresh,
                       float* __restrict__ A) {
    int r = blockIdx.x * 256 + threadIdx.x;
    int b = blockIdx.y;
    size_t idx = (size_t)b * NSQ + r;
    float v = x2[idx];
    unsigned long long key = make_key(v, (unsigned)r);
    float a = (key >= thresh[b]) ? v : 0.f;
    int i = r / NN, j = r - i * NN;
    if (i == j && a == 0.f) a = 1.f;
    A[idx] = a;
}

__global__ void deg_k(const float* __restrict__ A, float* __restrict__ dinv) {
    int b = blockIdx.x;
    int j = threadIdx.x;
    if (j >= NN) return;
    const float* Ab = A + (size_t)b * NSQ;
    float acc = 0.f;
    #pragma unroll 4
    for (int i = 0; i < NN; i++) acc += Ab[(size_t)i * NN + j];
    float dv = rsqrtf(acc);
    if (isinf(dv)) dv = 0.f;
    dinv[b * NN + j] = dv;
}

__global__ void an_k(const float* __restrict__ A, const float* __restrict__ dinv,
                     bf16* __restrict__ anh, bf16* __restrict__ anl,
                     float* __restrict__ rs) {
    int i = blockIdx.x, b = blockIdx.y;
    int tid = threadIdx.x;   // 128
    const float* dv = dinv + b * NN;
    size_t roff = (size_t)b * NSQ + (size_t)i * NN;
    float di = dv[i];
    float acc = 0.f;
    for (int j = tid; j < NN; j += 128) {
        float v = A[roff + j] * di * dv[j];
        fsplit(v, &anh[roff + j], &anl[roff + j]);
        acc += v;
    }
    __shared__ float sb[128];
    sb[tid] = acc;
    __syncthreads();
    for (int s = 64; s > 0; s >>= 1) {
        if (tid < s) sb[tid] += sb[tid + s];
        __syncthreads();
    }
    if (tid == 0) rs[b * NN + i] = sb[0] * (1.f / NN);
}

// =============== pure-bf16 split tensor-core GEMM ==============================
// C[M,N] = (Ah+Al)(Bh+Bl) via 3 products, f32 accumulate.
// A: gmem [M][lda] bf16 pair. B: gmem [K][ldb] bf16 pair.
// EPI: 0 none, 1 relu+bias[n], 2 relu+bias[n]+skip, 3 relu+bias[m]
// OUTF bit0: fp32 C; bit1: split bf16 C.
#define BM 128
#define BN 64
#define BK 32
#define BKP 40   // A row pad: 80B stride, ldmatrix conflict-free
#define BNP 72   // B row pad: 144B stride, ldmatrix conflict-free

__device__ __forceinline__ void ldm_x4(uint32_t* r, uint32_t a) {
    asm volatile("ldmatrix.sync.aligned.m8n8.x4.shared.b16 {%0,%1,%2,%3}, [%4];"
        : "=r"(r[0]), "=r"(r[1]), "=r"(r[2]), "=r"(r[3]) : "r"(a));
}
__device__ __forceinline__ void ldm_x2t(uint32_t* r, uint32_t a) {
    asm volatile("ldmatrix.sync.aligned.m8n8.x2.trans.shared.b16 {%0,%1}, [%2];"
        : "=r"(r[0]), "=r"(r[1]) : "r"(a));
}
__device__ __forceinline__ void mma16816(float* d, const uint32_t* a, const uint32_t* b) {
    asm volatile("mma.sync.aligned.m16n8k16.row.col.f32.bf16.bf16.f32 "
        "{%0,%1,%2,%3}, {%4,%5,%6,%7}, {%8,%9}, {%0,%1,%2,%3};"
        : "+f"(d[0]), "+f"(d[1]), "+f"(d[2]), "+f"(d[3])
        : "r"(a[0]), "r"(a[1]), "r"(a[2]), "r"(a[3]), "r"(b[0]), "r"(b[1]));
}

template<int EPI, int TRANSOUT, int OUTF>
__global__ void __launch_bounds__(256)
bgemm_k(const bf16* __restrict__ Ah, const bf16* __restrict__ Al, size_t sA, int lda,
        const bf16* __restrict__ Bh, const bf16* __restrict__ Bl, size_t sB, int ldb,
        const float* __restrict__ bias,
        const float* __restrict__ skip, size_t sS, int lds,
        float* __restrict__ Cf, bf16* __restrict__ Ch, bf16* __restrict__ Cl,
        size_t sC, int ldc, int M, int N, int K) {
    int bz = blockIdx.z;
    Ah += (size_t)bz * sA; Al += (size_t)bz * sA;
    Bh += (size_t)bz * sB; Bl += (size_t)bz * sB;
    if (EPI == 2) skip += (size_t)bz * sS;

    int n0 = blockIdx.x * BN;
    int m0 = blockIdx.y * BM;

    __shared__ bf16 sAm[2][BM][BKP];
    __shared__ bf16 sBt[2][BK][BNP];

    int tid = threadIdx.x;
    int warp = tid >> 5, lane = tid & 31;
    int wm = (warp >> 1) * 32;
    int wn = (warp & 1) * 32;
    int gid = lane >> 2, tig = lane & 3;

    float acc[2][4][4] = {};

    uint32_t aB[2], bB[2];
    aB[0] = (uint32_t)__cvta_generic_to_shared(&sAm[0][wm + (lane & 15)][(lane >> 4) * 8]);
    aB[1] = (uint32_t)__cvta_generic_to_shared(&sAm[1][wm + (lane & 15)][(lane >> 4) * 8]);
    bB[0] = (uint32_t)__cvta_generic_to_shared(&sBt[0][lane & 15][wn]);
    bB[1] = (uint32_t)__cvta_generic_to_shared(&sBt[1][lane & 15][wn]);

    const uint4 z4 = make_uint4(0, 0, 0, 0);

    for (int k0 = 0; k0 < K; k0 += BK) {
        // stage A: 1024 uint4 (hi+lo), 4 per thread
        #pragma unroll
        for (int it = 0; it < 4; it++) {
            int idx = tid + it * 256;
            int buf = idx >> 9;
            int r = (idx >> 2) & 127;
            int c = (idx & 3) * 8;
            int m = m0 + r, k = k0 + c;
            const bf16* src = buf ? Al : Ah;
            uint4 v = (m < M && k < K) ? *(const uint4*)&src[(size_t)m * lda + k] : z4;
            *(uint4*)&sAm[buf][r][c] = v;
        }
        // stage B: 512 uint4, 2 per thread
        #pragma unroll
        for (int it = 0; it < 2; it++) {
            int idx = tid + it * 256;
            int buf = idx >> 8;
            int r = (idx >> 3) & 31;
            int c = (idx & 7) * 8;
            int k = k0 + r, n = n0 + c;
            const bf16* src = buf ? Bl : Bh;
            uint4 v = (k < K && n < N) ? *(const uint4*)&src[(size_t)k * ldb + n] : z4;
            *(uint4*)&sBt[buf][r][c] = v;
        }
        __syncthreads();

        #pragma unroll
        for (int kc = 0; kc < 2; kc++) {
            uint32_t ah[2][4], al[2][4];
            ldm_x4(ah[0], aB[0] + kc * 32);
            ldm_x4(ah[1], aB[0] + 1280 + kc * 32);   // +16 rows * 80B
            ldm_x4(al[0], aB[1] + kc * 32);
            ldm_x4(al[1], aB[1] + 1280 + kc * 32);
            #pragma unroll
            for (int ni = 0; ni < 4; ni++) {
                uint32_t bh[2], bl[2];
                ldm_x2t(bh, bB[0] + kc * 2304 + ni * 16);  // +16 k-rows * 144B
                ldm_x2t(bl, bB[1] + kc * 2304 + ni * 16);
                #pragma unroll
                for (int mi = 0; mi < 2; mi++) {
                    mma16816(acc[mi][ni], ah[mi], bh);
                    mma16816(acc[mi][ni], al[mi], bh);
                    mma16816(acc[mi][ni], ah[mi], bl);
                }
            }
        }
        __syncthreads();
    }

    // epilogue
    #pragma unroll
    for (int mi = 0; mi < 2; mi++) {
        #pragma unroll
        for (int ni = 0; ni < 4; ni++) {
            int cbase = n0 + wn + ni * 8 + 2 * tig;
            #pragma unroll
            for (int h = 0; h < 2; h++) {
                int m = m0 + wm + mi * 16 + gid + h * 8;
                if (m >= M) continue;
                #pragma unroll
                for (int e = 0; e < 2; e++) {
                    int n = cbase + e;
                    if (n >= N) continue;
                    float v = acc[mi][ni][h * 2 + e];
                    if (EPI == 3) v += bias[m];
                    else if (bias) v += bias[n];
                    if (EPI == 2) v += skip[(size_t)m * lds + n];
                    if (EPI >= 1) v = fmaxf(v, 0.f);
                    size_t off = TRANSOUT ? ((size_t)n * ldc + m) : ((size_t)m * ldc + n);
                    if (OUTF & 1) Cf[(size_t)bz * sC + off] = v;
                    if (OUTF & 2) fsplit(v, &Ch[(size_t)bz * sC + off], &Cl[(size_t)bz * sC + off]);
                }
            }
        }
    }
}

// ---------------- head (consumes Y2^T) ------------------------------------------
__global__ void head_k(const float* __restrict__ Y2T, const float* __restrict__ rs,
                       const float* __restrict__ b2, const float* __restrict__ fcw,
                       const float* __restrict__ fcb, float* __restrict__ out) {
    int b = blockIdx.x;
    int f = threadIdx.x;   // feature g
    const float* Y = Y2T + (size_t)b * S_HN + (size_t)f * NN;
    const float* r = rs + b * NN;
    float acc = 0.f;
    for (int i = 0; i < NN; i++) acc += r[i] * Y[i];
    acc += b2[f];
    float pf = fmaxf(acc, 0.f);
    __shared__ float sp[HH];
    sp[f] = pf;
    __syncthreads();
    if (f < 2) {
        float o = fcb[f];
        for (int q = 0; q < HH; q++) o += sp[q] * fcw[q * 2 + f];
        out[b * 2 + f] = o;
    }
}

// ---------------------------------------------------------------------------------
extern "C" void kernel_launch(void* const* d_in, const int* in_sizes, int n_in,
                              void* d_out, int out_size) {
    const float* x      = (const float*)d_in[0];
    const float* enc1_w = (const float*)d_in[2];
    const float* enc1_b = (const float*)d_in[3];
    const float* enc2_w = (const float*)d_in[4];
    const float* enc2_b = (const float*)d_in[5];
    const float* dec2_w = (const float*)d_in[6];
    const float* dec2_b = (const float*)d_in[7];
    const float* dec1_w = (const float*)d_in[8];
    const float* dec1_b = (const float*)d_in[9];
    const float* gcn1_w = (const float*)d_in[10];
    const float* gcn1_b = (const float*)d_in[11];
    const float* gcn2_w = (const float*)d_in[12];
    const float* gcn2_b = (const float*)d_in[13];
    const float* fc_w   = (const float*)d_in[14];
    const float* fc_b   = (const float*)d_in[15];
    float* out = (float*)d_out;

    float *xf, *delta, *out1, *y2t, *dinv, *rs;
    bf16 *ah, *al, *anh, *anl, *o1h, *o1l, *o2ah, *o2al, *o2th, *o2tl;
    bf16 *y1h, *y1l, *h1h, *h1l, *wh, *wl;
    unsigned long long* thresh;
    cudaGetSymbolAddress((void**)&xf, g_xf);
    cudaGetSymbolAddress((void**)&delta, g_delta);
    cudaGetSymbolAddress((void**)&out1, g_out1);
    cudaGetSymbolAddress((void**)&y2t, g_y2t);
    cudaGetSymbolAddress((void**)&ah, g_ah);
    cudaGetSymbolAddress((void**)&al, g_al);
    cudaGetSymbolAddress((void**)&anh, g_anh);
    cudaGetSymbolAddress((void**)&anl, g_anl);
    cudaGetSymbolAddress((void**)&o1h, g_o1h);
    cudaGetSymbolAddress((void**)&o1l, g_o1l);
    cudaGetSymbolAddress((void**)&o2ah, g_o2ah);
    cudaGetSymbolAddress((void**)&o2al, g_o2al);
    cudaGetSymbolAddress((void**)&o2th, g_o2th);
    cudaGetSymbolAddress((void**)&o2tl, g_o2tl);
    cudaGetSymbolAddress((void**)&y1h, g_y1h);
    cudaGetSymbolAddress((void**)&y1l, g_y1l);
    cudaGetSymbolAddress((void**)&h1h, g_h1h);
    cudaGetSymbolAddress((void**)&h1l, g_h1l);
    cudaGetSymbolAddress((void**)&wh, g_wh);
    cudaGetSymbolAddress((void**)&wl, g_wl);
    cudaGetSymbolAddress((void**)&thresh, g_thresh);
    cudaGetSymbolAddress((void**)&dinv, g_dinv);
    cudaGetSymbolAddress((void**)&rs, g_rs);

    // weight prep (cheap, deterministic)
    wsplit_k<<<200, 256>>>(enc1_w, wh + W_E1, wl + W_E1, 51200);
    wsplit_k<<<200, 256>>>(enc2_w, wh + W_E2, wl + W_E2, 51200);
    wsplit_k<<<200, 256>>>(dec2_w, wh + W_D2, wl + W_D2, 51200);
    wsplit_k<<<200, 256>>>(dec1_w, wh + W_D1, wl + W_D1, 51200);
    wsplit_k<<<200, 256>>>(gcn1_w, wh + W_G1, wl + W_G1, 51200);
    wtsplit_k<<<64, 256>>>(gcn2_w, wh + W_G2T, wl + W_G2T);

    // 0) fisher + split
    fisher_k<<<dim3(625, BATCH), 256>>>(x, xf, ah, al);

    // 1) out1 = relu(xf @ enc1_w + b), TRANSOUT -> [H][N], fp32 + split
    bgemm_k<1, 1, 3><<<dim3(2, 4, BATCH), 256>>>(
        ah, al, NSQ, NN, wh + W_E1, wl + W_E1, 0, HH, enc1_b,
        nullptr, 0, 0, out1, o1h, o1l, S_HN, NN, NN, HH, NN);

    // 2) out2a = relu(out1 @ enc2_w + b)  [128][128] split only
    bgemm_k<1, 0, 2><<<dim3(2, 1, BATCH), 256>>>(
        o1h, o1l, S_HN, NN, wh + W_E2, wl + W_E2, 0, HH, enc2_b,
        nullptr, 0, 0, nullptr, o2ah, o2al, S_HH, HH, HH, HH, NN);

    // 3) out2 = relu(out2a @ dec2_w + b + out1), TRANSOUT -> out2T [N][H] split
    bgemm_k<2, 1, 2><<<dim3(7, 1, BATCH), 256>>>(
        o2ah, o2al, S_HH, HH, wh + W_D2, wl + W_D2, 0, NN, dec2_b,
        out1, S_HN, NN, nullptr, o2th, o2tl, S_HN, HH, HH, NN, HH);

    // 4) delta = out2T @ dec1_w + b  [400][400] fp32
    bgemm_k<0, 0, 1><<<dim3(7, 4, BATCH), 256>>>(
        o2th, o2tl, S_HN, HH, wh + W_D1, wl + W_D1, 0, NN, dec1_b,
        nullptr, 0, 0, delta, nullptr, nullptr, NSQ, NN, NN, NN, HH);

    // 5) x2 = xf + 0.5*(delta+delta^T)*(1-eye), + split (overwrites ah/al)
    sym_k<<<dim3(13, 13, BATCH), dim3(32, 32)>>>(xf, delta, ah, al);

    // 6) exact top-k threshold
    radix_select_k<<<BATCH, 512>>>(xf, thresh);

    // 7) A = masked x2 (+ self loops) -> delta buffer
    mask_k<<<dim3(625, BATCH), 256>>>(xf, thresh, delta);

    // 8) dinv
    deg_k<<<BATCH, 512>>>(delta, dinv);

    // 9) An split + row means
    an_k<<<dim3(NN, BATCH), 128>>>(delta, dinv, anh, anl, rs);

    // 10) Y1 = x2 @ gcn1_w, TRANSOUT -> Y1T [H][N] split
    bgemm_k<0, 1, 2><<<dim3(2, 4, BATCH), 256>>>(
        ah, al, NSQ, NN, wh + W_G1, wl + W_G1, 0, HH, nullptr,
        nullptr, 0, 0, nullptr, y1h, y1l, S_HN, NN, NN, HH, NN);

    // 11) h1T = relu(Y1T @ An + gcn1_b[m])  [H][N] split
    bgemm_k<3, 0, 2><<<dim3(7, 1, BATCH), 256>>>(
        y1h, y1l, S_HN, NN, anh, anl, NSQ, NN, gcn1_b,
        nullptr, 0, 0, nullptr, h1h, h1l, S_HN, NN, HH, NN, NN);

    // 12) Y2T = gcn2_wT @ h1T  [H][N] fp32
    bgemm_k<0, 0, 1><<<dim3(7, 1, BATCH), 256>>>(
        wh + W_G2T, wl + W_G2T, 0, HH, h1h, h1l, S_HN, NN, nullptr,
        nullptr, 0, 0, y2t, nullptr, nullptr, S_HN, NN, HH, NN, HH);

    // 13) head
    head_k<<<BATCH, HH>>>(y2t, rs, gcn2_b, fc_w, fc_b, out);
}

// round 5
// speedup vs baseline: 2.6116x; 1.3319x over previous
#include <cuda_runtime.h>
#include <cuda_bf16.h>
#include <cstdint>

#define EPS 1e-9f
#define BATCH 128
#define NN 400
#define HH 128
#define NSQ (NN * NN)          // 160000
#define S_HN (HH * NN)         // 51200
#define S_HH (HH * HH)         // 16384
#define KTOP 32000

typedef __nv_bfloat16 bf16;
typedef unsigned long long ull;

// ---------------- scratch -----------------------------------------------------
__device__ float g_xf[BATCH * NSQ];         // xf then x2 (in place)
__device__ float g_delta[BATCH * NSQ];      // delta (AE output)
__device__ float g_out1[BATCH * S_HN];      // out1 fp32 (skip operand)
__device__ float g_y2t[BATCH * S_HN];       // Y2^T fp32
__device__ bf16 g_ah[BATCH * NSQ], g_al[BATCH * NSQ];     // xf then x2 split
__device__ bf16 g_anh[BATCH * NSQ], g_anl[BATCH * NSQ];   // An split
__device__ bf16 g_o1h[BATCH * S_HN], g_o1l[BATCH * S_HN]; // out1 [H][N]
__device__ bf16 g_o2ah[BATCH * S_HH], g_o2al[BATCH * S_HH];
__device__ bf16 g_o2th[BATCH * S_HN], g_o2tl[BATCH * S_HN]; // out2^T [N][H]
__device__ bf16 g_y1h[BATCH * S_HN], g_y1l[BATCH * S_HN];   // Y1^T [H][N]
__device__ bf16 g_h1h[BATCH * S_HN], g_h1l[BATCH * S_HN];   // h1^T [H][N]
__device__ bf16 g_wh[272384], g_wl[272384];
__device__ ull g_thresh[BATCH];
__device__ float g_dinv[BATCH * NN];
__device__ float g_rs[BATCH * NN];

#define W_E1 0
#define W_E2 51200
#define W_D2 102400
#define W_D1 153600
#define W_G1 204800
#define W_G2T 256000

__device__ __forceinline__ void fsplit(float v, bf16* h, bf16* l) {
    bf16 hh = __float2bfloat16(v);
    *h = hh;
    *l = __float2bfloat16(v - __bfloat162float(hh));
}

// ---------------- weight prep --------------------------------------------------
__global__ void wsplit_k(const float* __restrict__ w, bf16* __restrict__ h,
                         bf16* __restrict__ l, int n) {
    int i = blockIdx.x * 256 + threadIdx.x;
    if (i < n) fsplit(w[i], &h[i], &l[i]);
}
__global__ void wtsplit_k(const float* __restrict__ w, bf16* __restrict__ h,
                          bf16* __restrict__ l) {
    int i = blockIdx.x * 256 + threadIdx.x;
    int g = i >> 7, f = i & 127;
    fsplit(w[f * HH + g], &h[i], &l[i]);
}

// ---------------- fisher + split ------------------------------------------------
__global__ void fisher_k(const float* __restrict__ x, float* __restrict__ xf,
                         bf16* __restrict__ xh, bf16* __restrict__ xl) {
    int r = blockIdx.x * 256 + threadIdx.x;
    int b = blockIdx.y;
    size_t base = (size_t)b * NSQ;
    float x00 = x[base];
    float d = 0.5f * __logf((1.f + x00 + EPS) / (1.f - x00 + EPS));
    float v = x[base + r];
    float f = 0.5f * __logf((1.f + v + EPS) / (1.f - v + EPS));
    float o = f / d;
    xf[base + r] = o;
    fsplit(o, &xh[base + r], &xl[base + r]);
}

// ---------------- symmetrize + split -------------------------------------------
__global__ void sym_k(float* __restrict__ xf, const float* __restrict__ delta,
                      bf16* __restrict__ xh, bf16* __restrict__ xl) {
    int b = blockIdx.z;
    int j0 = blockIdx.x * 32, i0 = blockIdx.y * 32;
    int tx = threadIdx.x, ty = threadIdx.y;
    __shared__ float sh[32][33];
    size_t base = (size_t)b * NSQ;
    int lr = j0 + ty, lc = i0 + tx;
    sh[ty][tx] = (lr < NN && lc < NN) ? delta[base + (size_t)lr * NN + lc] : 0.f;
    __syncthreads();
    int i = i0 + ty, j = j0 + tx;
    if (i < NN && j < NN) {
        size_t idx = base + (size_t)i * NN + j;
        float v = xf[idx];
        if (i != j) v += 0.5f * (delta[idx] + sh[tx][ty]);
        xf[idx] = v;
        fsplit(v, &xh[idx], &xl[idx]);
    }
}

// ---------------- keys -----------------------------------------------------------
__device__ __forceinline__ unsigned make_vkey(float v) {
    unsigned u = __float_as_uint(v);
    return (u & 0x80000000u) ? ~u : (u | 0x80000000u);
}
__device__ __forceinline__ ull make_key(float v, unsigned t) {
    return ((ull)make_vkey(v) << 32) | (ull)(~t);
}

// ---------------- exact top-k threshold: 4 value passes + tie resolve -----------
__global__ void radix_select_k(const float* __restrict__ x2,
                               ull* __restrict__ thresh) {
    const int b = blockIdx.x;
    const float* xp = x2 + (size_t)b * NSQ;
    __shared__ unsigned hist[16][256];
    __shared__ unsigned total[256];
    __shared__ unsigned s_prefix, s_rem, s_cnt;
    __shared__ unsigned buf[4096];
    int tid = threadIdx.x;            // 512
    int wid = tid >> 5, lane = tid & 31;
    if (tid == 0) { s_prefix = 0; s_rem = KTOP; s_cnt = 0; }
    __syncthreads();

    // --- 4 passes over the 32-bit value key ---
    for (int pass = 0; pass < 4; pass++) {
        int shift = 24 - 8 * pass;
        for (int i = tid; i < 16 * 256; i += 512) ((unsigned*)hist)[i] = 0;
        __syncthreads();
        unsigned pref = s_prefix;
        int hs = shift + 8;
        for (int t = tid; t < 160256; t += 512) {
            bool inr = t < NSQ;
            unsigned vk = inr ? make_vkey(xp[t]) : 0;
            bool ok = inr && ((hs >= 32) || ((vk >> hs) == (pref >> hs)));
            unsigned bin = (vk >> shift) & 255;
            unsigned active = __ballot_sync(0xffffffffu, ok);
            if (ok) {
                unsigned peers = __match_any_sync(active, bin);
                int leader = __ffs(peers) - 1;
                if (lane == leader) atomicAdd(&hist[wid][bin], __popc(peers));
            }
        }
        __syncthreads();
        for (int i = tid; i < 256; i += 512) {
            unsigned s = 0;
            #pragma unroll
            for (int w = 0; w < 16; w++) s += hist[w][i];
            total[i] = s;
        }
        __syncthreads();
        if (tid == 0) {
            unsigned rem = s_rem, cum = 0;
            int chosen = 0;
            for (int bin = 255; bin >= 0; bin--) {
                unsigned c = total[bin];
                if (cum + c >= rem) { chosen = bin; s_rem = rem - cum; break; }
                cum += c;
            }
            s_prefix |= ((unsigned)chosen << shift);
        }
        __syncthreads();
    }
    unsigned V = s_prefix, r = s_rem;

    // --- collect ties (elements with value key exactly V) ---
    for (int t = tid; t < NSQ; t += 512) {
        if (make_vkey(xp[t]) == V) {
            unsigned p = atomicAdd(&s_cnt, 1);
            if (p < 4096) buf[p] = ~(unsigned)t;
        }
    }
    __syncthreads();
    unsigned n = min(s_cnt, 4096u);
    if (tid == 0) { s_prefix = 0; s_rem = r; }
    __syncthreads();

    // --- resolve the low-32 index key among ties (in smem) ---
    for (int pass = 0; pass < 4; pass++) {
        int shift = 24 - 8 * pass;
        for (int i = tid; i < 16 * 256; i += 512) ((unsigned*)hist)[i] = 0;
        __syncthreads();
        unsigned pref = s_prefix;
        int hs = shift + 8;
        for (int t = tid; t < 4096; t += 512) {
            bool inr = t < n;
            unsigned k = inr ? buf[t] : 0;
            bool ok = inr && ((hs >= 32) || ((k >> hs) == (pref >> hs)));
            unsigned bin = (k >> shift) & 255;
            unsigned active = __ballot_sync(0xffffffffu, ok);
            if (ok) {
                unsigned peers = __match_any_sync(active, bin);
                int leader = __ffs(peers) - 1;
                if (lane == leader) atomicAdd(&hist[wid][bin], __popc(peers));
            }
        }
        __syncthreads();
        for (int i = tid; i < 256; i += 512) {
            unsigned s = 0;
            #pragma unroll
            for (int w = 0; w < 16; w++) s += hist[w][i];
            total[i] = s;
        }
        __syncthreads();
        if (tid == 0) {
            unsigned rem = s_rem, cum = 0;
            int chosen = 0;
            for (int bin = 255; bin >= 0; bin--) {
                unsigned c = total[bin];
                if (cum + c >= rem) { chosen = bin; s_rem = rem - cum; break; }
                cum += c;
            }
            s_prefix |= ((unsigned)chosen << shift);
        }
        __syncthreads();
    }
    if (tid == 0) thresh[b] = ((ull)V << 32) | (ull)s_prefix;
}

// ---------------- fused mask + column degree ------------------------------------
__global__ void deg_k(const float* __restrict__ x2, const ull* __restrict__ th,
                      float* __restrict__ dinv) {
    int b = blockIdx.x;
    int j = threadIdx.x;
    if (j >= NN) return;
    ull t = th[b];
    const float* xb = x2 + (size_t)b * NSQ;
    float acc = 0.f;
    #pragma unroll 4
    for (int i = 0; i < NN; i++) {
        unsigned r = (unsigned)(i * NN + j);
        float v = xb[r];
        float a = (make_key(v, r) >= t) ? v : 0.f;
        if (i == j && a == 0.f) a = 1.f;
        acc += a;
    }
    float dv = rsqrtf(acc);
    if (isinf(dv)) dv = 0.f;
    dinv[b * NN + j] = dv;
}

// ---------------- fused mask + An split + row means ------------------------------
__global__ void an_k(const float* __restrict__ x2, const ull* __restrict__ th,
                     const float* __restrict__ dinv,
                     bf16* __restrict__ anh, bf16* __restrict__ anl,
                     float* __restrict__ rs) {
    int i = blockIdx.x, b = blockIdx.y;
    int tid = threadIdx.x;   // 128
    ull t = th[b];
    const float* dv = dinv + b * NN;
    size_t roff = (size_t)b * NSQ + (size_t)i * NN;
    float di = dv[i];
    float acc = 0.f;
    for (int j = tid; j < NN; j += 128) {
        float v = x2[roff + j];
        unsigned r = (unsigned)(i * NN + j);
        float a = (make_key(v, r) >= t) ? v : 0.f;
        if (i == j && a == 0.f) a = 1.f;
        float w = a * di * dv[j];
        fsplit(w, &anh[roff + j], &anl[roff + j]);
        acc += w;
    }
    __shared__ float sb[128];
    sb[tid] = acc;
    __syncthreads();
    for (int s = 64; s > 0; s >>= 1) {
        if (tid < s) sb[tid] += sb[tid + s];
        __syncthreads();
    }
    if (tid == 0) rs[b * NN + i] = sb[0] * (1.f / NN);
}

// =============== cp.async double-buffered bf16 split GEMM =======================
#define BM 128
#define BN 64
#define BK 32
#define BKP 40
#define BNP 72
#define ABUF (BM * BKP * 2)        // 10240 B per hi/lo buffer
#define ASTG (2 * ABUF)            // 20480 B per stage
#define BBUF (BK * BNP * 2)        // 4608
#define BSTG (2 * BBUF)            // 9216
#define SMEM_TOT (2 * ASTG + 2 * BSTG)   // 59392

__device__ __forceinline__ void ldm_x4(uint32_t* r, uint32_t a) {
    asm volatile("ldmatrix.sync.aligned.m8n8.x4.shared.b16 {%0,%1,%2,%3}, [%4];"
        : "=r"(r[0]), "=r"(r[1]), "=r"(r[2]), "=r"(r[3]) : "r"(a));
}
__device__ __forceinline__ void ldm_x2t(uint32_t* r, uint32_t a) {
    asm volatile("ldmatrix.sync.aligned.m8n8.x2.trans.shared.b16 {%0,%1}, [%2];"
        : "=r"(r[0]), "=r"(r[1]) : "r"(a));
}
__device__ __forceinline__ void mma16816(float* d, const uint32_t* a, const uint32_t* b) {
    asm volatile("mma.sync.aligned.m16n8k16.row.col.f32.bf16.bf16.f32 "
        "{%0,%1,%2,%3}, {%4,%5,%6,%7}, {%8,%9}, {%0,%1,%2,%3};"
        : "+f"(d[0]), "+f"(d[1]), "+f"(d[2]), "+f"(d[3])
        : "r"(a[0]), "r"(a[1]), "r"(a[2]), "r"(a[3]), "r"(b[0]), "r"(b[1]));
}
__device__ __forceinline__ void cpa16(uint32_t dst, const bf16* src, bool p) {
    int sz = p ? 16 : 0;
    asm volatile("cp.async.cg.shared.global [%0], [%1], 16, %2;"
        :: "r"(dst), "l"(src), "r"(sz));
}
__device__ __forceinline__ void cp_commit() {
    asm volatile("cp.async.commit_group;");
}
template<int W> __device__ __forceinline__ void cp_wait() {
    asm volatile("cp.async.wait_group %0;" :: "n"(W));
}

// EPI: 0 none, 1 relu+bias[n], 2 relu+bias[n]+skip, 3 relu+bias[m]
// OUTF bit0: fp32 C; bit1: split bf16 C.
template<int EPI, int TRANSOUT, int OUTF>
__global__ void __launch_bounds__(256)
bgemm_k(const bf16* __restrict__ Ah, const bf16* __restrict__ Al, size_t sA, int lda,
        const bf16* __restrict__ Bh, const bf16* __restrict__ Bl, size_t sB, int ldb,
        const float* __restrict__ bias,
        const float* __restrict__ skip, size_t sS, int lds,
        float* __restrict__ Cf, bf16* __restrict__ Ch, bf16* __restrict__ Cl,
        size_t sC, int ldc, int M, int N, int K) {
    int bz = blockIdx.z;
    Ah += (size_t)bz * sA; Al += (size_t)bz * sA;
    Bh += (size_t)bz * sB; Bl += (size_t)bz * sB;
    if (EPI == 2) skip += (size_t)bz * sS;

    int n0 = blockIdx.x * BN;
    int m0 = blockIdx.y * BM;

    extern __shared__ bf16 dsm[];
    uint32_t smA = (uint32_t)__cvta_generic_to_shared(dsm);
    uint32_t smB = smA + 2 * ASTG;

    int tid = threadIdx.x;
    int warp = tid >> 5, lane = tid & 31;
    int wm = (warp >> 1) * 32;
    int wn = (warp & 1) * 32;
    int gid = lane >> 2, tig = lane & 3;

    // staging assignments (fixed per thread)
    const bf16* aSrc[4]; uint32_t aDst[4]; bool aPm[4]; int aC[4];
    #pragma unroll
    for (int it = 0; it < 4; it++) {
        int idx = tid + it * 256;
        int buf = idx >> 9;
        int rem = idx & 511;
        int r = rem >> 2, c = (rem & 3) * 8;
        int m = m0 + r;
        aPm[it] = m < M;
        aC[it] = c;
        aSrc[it] = (buf ? Al : Ah) + (size_t)(aPm[it] ? m : (M - 1)) * lda + c;
        aDst[it] = smA + buf * ABUF + (r * BKP + c) * 2;
    }
    const bf16* bSrc[2]; uint32_t bDst[2]; bool bPn[2]; int bR[2];
    #pragma unroll
    for (int it = 0; it < 2; it++) {
        int idx = tid + it * 256;
        int buf = idx >> 8;
        int rem = idx & 255;
        int r = rem >> 3, c = (rem & 7) * 8;
        bR[it] = r;
        bPn[it] = (n0 + c) < N;
        bSrc[it] = (buf ? Bl : Bh) + (size_t)r * ldb + (n0 + (bPn[it] ? c : 0));
        bDst[it] = smB + buf * BBUF + (r * BNP + c) * 2;
    }

    auto issue = [&](int k0, int stg) {
        #pragma unroll
        for (int it = 0; it < 4; it++)
            cpa16(aDst[it] + stg * ASTG, aSrc[it] + k0, aPm[it] && (k0 + aC[it] < K));
        #pragma unroll
        for (int it = 0; it < 2; it++)
            cpa16(bDst[it] + stg * BSTG, bSrc[it] + (size_t)k0 * ldb,
                  bPn[it] && (k0 + bR[it] < K));
        cp_commit();
    };

    float acc[2][4][4] = {};

    uint32_t aB0 = smA + ((wm + (lane & 15)) * BKP + (lane >> 4) * 8) * 2;
    uint32_t bB0 = smB + ((lane & 15) * BNP + wn) * 2;

    int nk = (K + BK - 1) / BK;
    issue(0, 0);
    for (int t = 0; t < nk; t++) {
        if (t + 1 < nk) { issue((t + 1) * BK, (t + 1) & 1); cp_wait<1>(); }
        else cp_wait<0>();
        __syncthreads();
        int stg = t & 1;
        uint32_t aH = aB0 + stg * ASTG;
        uint32_t aL = aH + ABUF;
        uint32_t bH = bB0 + stg * BSTG;
        uint32_t bL = bH + BBUF;
        #pragma unroll
        for (int kc = 0; kc < 2; kc++) {
            uint32_t ah[2][4], al[2][4];
            ldm_x4(ah[0], aH + kc * 32);
            ldm_x4(ah[1], aH + 16 * BKP * 2 + kc * 32);
            ldm_x4(al[0], aL + kc * 32);
            ldm_x4(al[1], aL + 16 * BKP * 2 + kc * 32);
            #pragma unroll
            for (int ni = 0; ni < 4; ni++) {
                uint32_t bh[2], bl[2];
                ldm_x2t(bh, bH + kc * 16 * BNP * 2 + ni * 16);
                ldm_x2t(bl, bL + kc * 16 * BNP * 2 + ni * 16);
                #pragma unroll
                for (int mi = 0; mi < 2; mi++) {
                    mma16816(acc[mi][ni], ah[mi], bh);
                    mma16816(acc[mi][ni], al[mi], bh);
                    mma16816(acc[mi][ni], ah[mi], bl);
                }
            }
        }
        __syncthreads();
    }

    // epilogue
    #pragma unroll
    for (int mi = 0; mi < 2; mi++) {
        #pragma unroll
        for (int ni = 0; ni < 4; ni++) {
            int cbase = n0 + wn + ni * 8 + 2 * tig;
            #pragma unroll
            for (int h = 0; h < 2; h++) {
                int m = m0 + wm + mi * 16 + gid + h * 8;
                if (m >= M) continue;
                #pragma unroll
                for (int e = 0; e < 2; e++) {
                    int n = cbase + e;
                    if (n >= N) continue;
                    float v = acc[mi][ni][h * 2 + e];
                    if (EPI == 3) v += bias[m];
                    else if (bias) v += bias[n];
                    if (EPI == 2) v += skip[(size_t)m * lds + n];
                    if (EPI >= 1) v = fmaxf(v, 0.f);
                    size_t off = TRANSOUT ? ((size_t)n * ldc + m) : ((size_t)m * ldc + n);
                    if (OUTF & 1) Cf[(size_t)bz * sC + off] = v;
                    if (OUTF & 2) fsplit(v, &Ch[(size_t)bz * sC + off], &Cl[(size_t)bz * sC + off]);
                }
            }
        }
    }
}

// ---------------- head ------------------------------------------------------------
__global__ void head_k(const float* __restrict__ Y2T, const float* __restrict__ rs,
                       const float* __restrict__ b2, const float* __restrict__ fcw,
                       const float* __restrict__ fcb, float* __restrict__ out) {
    int b = blockIdx.x;
    int f = threadIdx.x;
    const float* Y = Y2T + (size_t)b * S_HN + (size_t)f * NN;
    const float* r = rs + b * NN;
    float acc = 0.f;
    for (int i = 0; i < NN; i++) acc += r[i] * Y[i];
    acc += b2[f];
    float pf = fmaxf(acc, 0.f);
    __shared__ float sp[HH];
    sp[f] = pf;
    __syncthreads();
    if (f < 2) {
        float o = fcb[f];
        for (int q = 0; q < HH; q++) o += sp[q] * fcw[q * 2 + f];
        out[b * 2 + f] = o;
    }
}

// -----------------------------------------------------------------------------------
extern "C" void kernel_launch(void* const* d_in, const int* in_sizes, int n_in,
                              void* d_out, int out_size) {
    const float* x      = (const float*)d_in[0];
    const float* enc1_w = (const float*)d_in[2];
    const float* enc1_b = (const float*)d_in[3];
    const float* enc2_w = (const float*)d_in[4];
    const float* enc2_b = (const float*)d_in[5];
    const float* dec2_w = (const float*)d_in[6];
    const float* dec2_b = (const float*)d_in[7];
    const float* dec1_w = (const float*)d_in[8];
    const float* dec1_b = (const float*)d_in[9];
    const float* gcn1_w = (const float*)d_in[10];
    const float* gcn1_b = (const float*)d_in[11];
    const float* gcn2_w = (const float*)d_in[12];
    const float* gcn2_b = (const float*)d_in[13];
    const float* fc_w   = (const float*)d_in[14];
    const float* fc_b   = (const float*)d_in[15];
    float* out = (float*)d_out;

    float *xf, *delta, *out1, *y2t, *dinv, *rs;
    bf16 *ah, *al, *anh, *anl, *o1h, *o1l, *o2ah, *o2al, *o2th, *o2tl;
    bf16 *y1h, *y1l, *h1h, *h1l, *wh, *wl;
    ull* thresh;
    cudaGetSymbolAddress((void**)&xf, g_xf);
    cudaGetSymbolAddress((void**)&delta, g_delta);
    cudaGetSymbolAddress((void**)&out1, g_out1);
    cudaGetSymbolAddress((void**)&y2t, g_y2t);
    cudaGetSymbolAddress((void**)&ah, g_ah);
    cudaGetSymbolAddress((void**)&al, g_al);
    cudaGetSymbolAddress((void**)&anh, g_anh);
    cudaGetSymbolAddress((void**)&anl, g_anl);
    cudaGetSymbolAddress((void**)&o1h, g_o1h);
    cudaGetSymbolAddress((void**)&o1l, g_o1l);
    cudaGetSymbolAddress((void**)&o2ah, g_o2ah);
    cudaGetSymbolAddress((void**)&o2al, g_o2al);
    cudaGetSymbolAddress((void**)&o2th, g_o2th);
    cudaGetSymbolAddress((void**)&o2tl, g_o2tl);
    cudaGetSymbolAddress((void**)&y1h, g_y1h);
    cudaGetSymbolAddress((void**)&y1l, g_y1l);
    cudaGetSymbolAddress((void**)&h1h, g_h1h);
    cudaGetSymbolAddress((void**)&h1l, g_h1l);
    cudaGetSymbolAddress((void**)&wh, g_wh);
    cudaGetSymbolAddress((void**)&wl, g_wl);
    cudaGetSymbolAddress((void**)&thresh, g_thresh);
    cudaGetSymbolAddress((void**)&dinv, g_dinv);
    cudaGetSymbolAddress((void**)&rs, g_rs);

    cudaFuncSetAttribute((const void*)&bgemm_k<1,1,3>, cudaFuncAttributeMaxDynamicSharedMemorySize, SMEM_TOT);
    cudaFuncSetAttribute((const void*)&bgemm_k<1,0,2>, cudaFuncAttributeMaxDynamicSharedMemorySize, SMEM_TOT);
    cudaFuncSetAttribute((const void*)&bgemm_k<2,1,2>, cudaFuncAttributeMaxDynamicSharedMemorySize, SMEM_TOT);
    cudaFuncSetAttribute((const void*)&bgemm_k<0,0,1>, cudaFuncAttributeMaxDynamicSharedMemorySize, SMEM_TOT);
    cudaFuncSetAttribute((const void*)&bgemm_k<0,1,2>, cudaFuncAttributeMaxDynamicSharedMemorySize, SMEM_TOT);
    cudaFuncSetAttribute((const void*)&bgemm_k<3,0,2>, cudaFuncAttributeMaxDynamicSharedMemorySize, SMEM_TOT);

    // weight prep
    wsplit_k<<<200, 256>>>(enc1_w, wh + W_E1, wl + W_E1, 51200);
    wsplit_k<<<200, 256>>>(enc2_w, wh + W_E2, wl + W_E2, 51200);
    wsplit_k<<<200, 256>>>(dec2_w, wh + W_D2, wl + W_D2, 51200);
    wsplit_k<<<200, 256>>>(dec1_w, wh + W_D1, wl + W_D1, 51200);
    wsplit_k<<<200, 256>>>(gcn1_w, wh + W_G1, wl + W_G1, 51200);
    wtsplit_k<<<64, 256>>>(gcn2_w, wh + W_G2T, wl + W_G2T);

    // 0) fisher + split
    fisher_k<<<dim3(625, BATCH), 256>>>(x, xf, ah, al);

    // 1) out1 = relu(xf @ enc1_w + b) -> [H][N] fp32 + split
    bgemm_k<1, 1, 3><<<dim3(2, 4, BATCH), 256, SMEM_TOT>>>(
        ah, al, NSQ, NN, wh + W_E1, wl + W_E1, 0, HH, enc1_b,
        nullptr, 0, 0, out1, o1h, o1l, S_HN, NN, NN, HH, NN);

    // 2) out2a = relu(out1 @ enc2_w + b)
    bgemm_k<1, 0, 2><<<dim3(2, 1, BATCH), 256, SMEM_TOT>>>(
        o1h, o1l, S_HN, NN, wh + W_E2, wl + W_E2, 0, HH, enc2_b,
        nullptr, 0, 0, nullptr, o2ah, o2al, S_HH, HH, HH, HH, NN);

    // 3) out2 = relu(out2a @ dec2_w + b + out1) -> out2T [N][H] split
    bgemm_k<2, 1, 2><<<dim3(7, 1, BATCH), 256, SMEM_TOT>>>(
        o2ah, o2al, S_HH, HH, wh + W_D2, wl + W_D2, 0, NN, dec2_b,
        out1, S_HN, NN, nullptr, o2th, o2tl, S_HN, HH, HH, NN, HH);

    // 4) delta = out2T @ dec1_w + b  [400][400] fp32
    bgemm_k<0, 0, 1><<<dim3(7, 4, BATCH), 256, SMEM_TOT>>>(
        o2th, o2tl, S_HN, HH, wh + W_D1, wl + W_D1, 0, NN, dec1_b,
        nullptr, 0, 0, delta, nullptr, nullptr, NSQ, NN, NN, NN, HH);

    // 5) x2 = xf + 0.5*(delta+delta^T)*(1-eye), + split
    sym_k<<<dim3(13, 13, BATCH), dim3(32, 32)>>>(xf, delta, ah, al);

    // 6) top-k threshold (4 value passes + tie resolve)
    radix_select_k<<<BATCH, 512>>>(xf, thresh);

    // 7) fused mask + column degrees
    deg_k<<<BATCH, 512>>>(xf, thresh, dinv);

    // 8) fused mask + An split + row means
    an_k<<<dim3(NN, BATCH), 128>>>(xf, thresh, dinv, anh, anl, rs);

    // 9) Y1 = x2 @ gcn1_w -> Y1T [H][N] split
    bgemm_k<0, 1, 2><<<dim3(2, 4, BATCH), 256, SMEM_TOT>>>(
        ah, al, NSQ, NN, wh + W_G1, wl + W_G1, 0, HH, nullptr,
        nullptr, 0, 0, nullptr, y1h, y1l, S_HN, NN, NN, HH, NN);

    // 10) h1T = relu(Y1T @ An + gcn1_b[m])
    bgemm_k<3, 0, 2><<<dim3(7, 1, BATCH), 256, SMEM_TOT>>>(
        y1h, y1l, S_HN, NN, anh, anl, NSQ, NN, gcn1_b,
        nullptr, 0, 0, nullptr, h1h, h1l, S_HN, NN, HH, NN, NN);

    // 11) Y2T = gcn2_wT @ h1T  fp32
    bgemm_k<0, 0, 1><<<dim3(7, 1, BATCH), 256, SMEM_TOT>>>(
        wh + W_G2T, wl + W_G2T, 0, HH, h1h, h1l, S_HN, NN, nullptr,
        nullptr, 0, 0, y2t, nullptr, nullptr, S_HN, NN, HH, NN, HH);

    // 12) head
    head_k<<<BATCH, HH>>>(y2t, rs, gcn2_b, fc_w, fc_b, out);
}

// round 6
// speedup vs baseline: 3.4547x; 1.3228x over previous
#include <cuda_runtime.h>
#include <cuda_bf16.h>
#include <cstdint>

#define EPS 1e-9f
#define BATCH 128
#define NN 400
#define HH 128
#define NSQ (NN * NN)          // 160000
#define NQ4 (NSQ / 4)          // 40000
#define S_HN (HH * NN)         // 51200
#define S_HH (HH * HH)         // 16384
#define KTOP 32000

typedef __nv_bfloat16 bf16;
typedef unsigned long long ull;

// ---------------- scratch -----------------------------------------------------
__device__ float g_xf[BATCH * NSQ];         // xf then x2 (in place)
__device__ float g_delta[BATCH * NSQ];      // delta (AE output)
__device__ float g_out1[BATCH * S_HN];      // out1 fp32 (skip operand)
__device__ float g_y2t[BATCH * S_HN];       // Y2^T fp32
__device__ bf16 g_ah[BATCH * NSQ], g_al[BATCH * NSQ];
__device__ bf16 g_anh[BATCH * NSQ], g_anl[BATCH * NSQ];
__device__ bf16 g_o1h[BATCH * S_HN], g_o1l[BATCH * S_HN];
__device__ bf16 g_o2ah[BATCH * S_HH], g_o2al[BATCH * S_HH];
__device__ bf16 g_o2th[BATCH * S_HN], g_o2tl[BATCH * S_HN];
__device__ bf16 g_y1h[BATCH * S_HN], g_y1l[BATCH * S_HN];
__device__ bf16 g_h1h[BATCH * S_HN], g_h1l[BATCH * S_HN];
__device__ bf16 g_wh[272384], g_wl[272384];
__device__ ull g_thresh[BATCH];
__device__ float g_dinv[BATCH * NN];
__device__ float g_rs[BATCH * NN];

#define W_E1 0
#define W_E2 51200
#define W_D2 102400
#define W_D1 153600
#define W_G1 204800
#define W_G2T 256000

__device__ __forceinline__ void fsplit(float v, bf16* h, bf16* l) {
    bf16 hh = __float2bfloat16(v);
    *h = hh;
    *l = __float2bfloat16(v - __bfloat162float(hh));
}
// pack 4 (v) into hi/lo uint2 words
__device__ __forceinline__ void fsplit4(const float* v, uint2* ph, uint2* pl) {
    unsigned short h[4], l[4];
    #pragma unroll
    for (int e = 0; e < 4; e++) {
        bf16 hh = __float2bfloat16(v[e]);
        h[e] = __bfloat16_as_ushort(hh);
        l[e] = __bfloat16_as_ushort(__float2bfloat16(v[e] - __bfloat162float(hh)));
    }
    ph->x = (unsigned)h[0] | ((unsigned)h[1] << 16);
    ph->y = (unsigned)h[2] | ((unsigned)h[3] << 16);
    pl->x = (unsigned)l[0] | ((unsigned)l[1] << 16);
    pl->y = (unsigned)l[2] | ((unsigned)l[3] << 16);
}

// ---------------- weight prep --------------------------------------------------
__global__ void wsplit_k(const float* __restrict__ w, bf16* __restrict__ h,
                         bf16* __restrict__ l, int n) {
    int i = blockIdx.x * 256 + threadIdx.x;
    if (i < n) fsplit(w[i], &h[i], &l[i]);
}
__global__ void wtsplit_k(const float* __restrict__ w, bf16* __restrict__ h,
                          bf16* __restrict__ l) {
    int i = blockIdx.x * 256 + threadIdx.x;
    int g = i >> 7, f = i & 127;
    fsplit(w[f * HH + g], &h[i], &l[i]);
}

// ---------------- fisher + split (vectorized) -----------------------------------
__global__ void fisher_k(const float* __restrict__ x, float* __restrict__ xf,
                         bf16* __restrict__ xh, bf16* __restrict__ xl) {
    int t = blockIdx.x * 256 + threadIdx.x;
    int b = blockIdx.y;
    if (t >= NQ4) return;
    size_t base = (size_t)b * NSQ;
    float x00 = x[base];
    float d = 0.5f * __logf((1.f + x00 + EPS) / (1.f - x00 + EPS));
    float rd = 1.f / d;
    float4 v = ((const float4*)(x + base))[t];
    float o[4];
    o[0] = 0.5f * __logf((1.f + v.x + EPS) / (1.f - v.x + EPS)) * rd;
    o[1] = 0.5f * __logf((1.f + v.y + EPS) / (1.f - v.y + EPS)) * rd;
    o[2] = 0.5f * __logf((1.f + v.z + EPS) / (1.f - v.z + EPS)) * rd;
    o[3] = 0.5f * __logf((1.f + v.w + EPS) / (1.f - v.w + EPS)) * rd;
    ((float4*)(xf + base))[t] = make_float4(o[0], o[1], o[2], o[3]);
    uint2 ph, pl;
    fsplit4(o, &ph, &pl);
    ((uint2*)(xh + base))[t] = ph;
    ((uint2*)(xl + base))[t] = pl;
}

// ---------------- symmetric-pair symmetrize + split -----------------------------
// block handles tile pair (ti,tj), ti<=tj; 91 pairs/batch
__global__ void sym2_k(float* __restrict__ xf, const float* __restrict__ delta,
                       bf16* __restrict__ xh, bf16* __restrict__ xl) {
    int b = blockIdx.y;
    int p = blockIdx.x;            // 0..90
    int ti = 0, rem = p;
    while (rem >= 13 - ti) { rem -= 13 - ti; ti++; }
    int tj = ti + rem;
    int i0 = ti * 32, j0 = tj * 32;
    int tx = threadIdx.x;          // 0..7 float4 group
    int ty = threadIdx.y;          // 0..31 row
    __shared__ float shA[32][33];
    __shared__ float shB[32][33];
    size_t base = (size_t)b * NSQ;
    bool diag = (ti == tj);

    // load A tile: delta rows i0+ty, cols j0+tx*4
    {
        int r = i0 + ty, c = j0 + tx * 4;
        float4 v = make_float4(0.f, 0.f, 0.f, 0.f);
        if (r < NN && c < NN) v = *(const float4*)&delta[base + (size_t)r * NN + c];
        shA[ty][tx * 4 + 0] = v.x; shA[ty][tx * 4 + 1] = v.y;
        shA[ty][tx * 4 + 2] = v.z; shA[ty][tx * 4 + 3] = v.w;
    }
    if (!diag) {
        int r = j0 + ty, c = i0 + tx * 4;
        float4 v = make_float4(0.f, 0.f, 0.f, 0.f);
        if (r < NN && c < NN) v = *(const float4*)&delta[base + (size_t)r * NN + c];
        shB[ty][tx * 4 + 0] = v.x; shB[ty][tx * 4 + 1] = v.y;
        shB[ty][tx * 4 + 2] = v.z; shB[ty][tx * 4 + 3] = v.w;
    }
    __syncthreads();

    // output tile A: rows i0+ty, cols j0+tx*4
    {
        int r = i0 + ty, c0 = j0 + tx * 4;
        if (r < NN && c0 < NN) {
            size_t idx = base + (size_t)r * NN + c0;
            float4 xv = *(const float4*)&xf[idx];
            float o[4] = {xv.x, xv.y, xv.z, xv.w};
            #pragma unroll
            for (int e = 0; e < 4; e++) {
                int c = c0 + e;
                float dT = diag ? shA[tx * 4 + e][ty] : shB[tx * 4 + e][ty];
                if (r != c) o[e] += 0.5f * (shA[ty][tx * 4 + e] + dT);
            }
            *(float4*)&xf[idx] = make_float4(o[0], o[1], o[2], o[3]);
            uint2 ph, pl;
            fsplit4(o, &ph, &pl);
            *(uint2*)&xh[idx] = ph;
            *(uint2*)&xl[idx] = pl;
        }
    }
    // output tile B: rows j0+ty, cols i0+tx*4
    if (!diag) {
        int r = j0 + ty, c0 = i0 + tx * 4;
        if (r < NN && c0 < NN) {
            size_t idx = base + (size_t)r * NN + c0;
            float4 xv = *(const float4*)&xf[idx];
            float o[4] = {xv.x, xv.y, xv.z, xv.w};
            #pragma unroll
            for (int e = 0; e < 4; e++) {
                int c = c0 + e;
                if (r != c) o[e] += 0.5f * (shB[ty][tx * 4 + e] + shA[tx * 4 + e][ty]);
            }
            *(float4*)&xf[idx] = make_float4(o[0], o[1], o[2], o[3]);
            uint2 ph, pl;
            fsplit4(o, &ph, &pl);
            *(uint2*)&xh[idx] = ph;
            *(uint2*)&xl[idx] = pl;
        }
    }
}

// ---------------- keys ------------------------------------------------------------
__device__ __forceinline__ unsigned make_vkey(float v) {
    unsigned u = __float_as_uint(v);
    return (u & 0x80000000u) ? ~u : (u | 0x80000000u);
}
__device__ __forceinline__ ull make_key(float v, unsigned t) {
    return ((ull)make_vkey(v) << 32) | (ull)(~t);
}

// ---------------- exact top-k: 4 value passes (vectorized) + tie resolve ---------
__global__ void radix_select_k(const float* __restrict__ x2,
                               ull* __restrict__ thresh) {
    const int b = blockIdx.x;
    const float4* xp4 = (const float4*)(x2 + (size_t)b * NSQ);
    __shared__ unsigned hist[16][256];
    __shared__ unsigned total[256];
    __shared__ unsigned s_prefix, s_rem, s_cnt;
    __shared__ unsigned buf[4096];
    int tid = threadIdx.x;            // 512
    int wid = tid >> 5, lane = tid & 31;
    if (tid == 0) { s_prefix = 0; s_rem = KTOP; s_cnt = 0; }
    __syncthreads();

    for (int pass = 0; pass < 4; pass++) {
        int shift = 24 - 8 * pass;
        for (int i = tid; i < 16 * 256; i += 512) ((unsigned*)hist)[i] = 0;
        __syncthreads();
        unsigned pref = s_prefix;
        int hs = shift + 8;
        for (int t = tid; t < 40448; t += 512) {
            bool inr = t < NQ4;
            float4 v = inr ? xp4[t] : make_float4(0.f, 0.f, 0.f, 0.f);
            float vv[4] = {v.x, v.y, v.z, v.w};
            #pragma unroll
            for (int e = 0; e < 4; e++) {
                unsigned vk = make_vkey(vv[e]);
                bool ok = inr && ((hs >= 32) || ((vk >> hs) == (pref >> hs)));
                unsigned bin = (vk >> shift) & 255;
                unsigned active = __ballot_sync(0xffffffffu, ok);
                if (ok) {
                    unsigned peers = __match_any_sync(active, bin);
                    int leader = __ffs(peers) - 1;
                    if (lane == leader) atomicAdd(&hist[wid][bin], __popc(peers));
                }
            }
        }
        __syncthreads();
        for (int i = tid; i < 256; i += 512) {
            unsigned s = 0;
            #pragma unroll
            for (int w = 0; w < 16; w++) s += hist[w][i];
            total[i] = s;
        }
        __syncthreads();
        if (tid == 0) {
            unsigned rem = s_rem, cum = 0;
            int chosen = 0;
            for (int bin = 255; bin >= 0; bin--) {
                unsigned c = total[bin];
                if (cum + c >= rem) { chosen = bin; s_rem = rem - cum; break; }
                cum += c;
            }
            s_prefix |= ((unsigned)chosen << shift);
        }
        __syncthreads();
    }
    unsigned V = s_prefix, r = s_rem;

    // collect ties
    for (int t = tid; t < NQ4; t += 512) {
        float4 v = xp4[t];
        float vv[4] = {v.x, v.y, v.z, v.w};
        #pragma unroll
        for (int e = 0; e < 4; e++) {
            if (make_vkey(vv[e]) == V) {
                unsigned p = atomicAdd(&s_cnt, 1);
                if (p < 4096) buf[p] = ~(unsigned)(t * 4 + e);
            }
        }
    }
    __syncthreads();
    unsigned n = min(s_cnt, 4096u);
    if (tid == 0) { s_prefix = 0; s_rem = r; }
    __syncthreads();

    for (int pass = 0; pass < 4; pass++) {
        int shift = 24 - 8 * pass;
        for (int i = tid; i < 16 * 256; i += 512) ((unsigned*)hist)[i] = 0;
        __syncthreads();
        unsigned pref = s_prefix;
        int hs = shift + 8;
        for (int t = tid; t < 4096; t += 512) {
            bool inr = t < n;
            unsigned k = inr ? buf[t] : 0;
            bool ok = inr && ((hs >= 32) || ((k >> hs) == (pref >> hs)));
            unsigned bin = (k >> shift) & 255;
            unsigned active = __ballot_sync(0xffffffffu, ok);
            if (ok) {
                unsigned peers = __match_any_sync(active, bin);
                int leader = __ffs(peers) - 1;
                if (lane == leader) atomicAdd(&hist[wid][bin], __popc(peers));
            }
        }
        __syncthreads();
        for (int i = tid; i < 256; i += 512) {
            unsigned s = 0;
            #pragma unroll
            for (int w = 0; w < 16; w++) s += hist[w][i];
            total[i] = s;
        }
        __syncthreads();
        if (tid == 0) {
            unsigned rem = s_rem, cum = 0;
            int chosen = 0;
            for (int bin = 255; bin >= 0; bin--) {
                unsigned c = total[bin];
                if (cum + c >= rem) { chosen = bin; s_rem = rem - cum; break; }
                cum += c;
            }
            s_prefix |= ((unsigned)chosen << shift);
        }
        __syncthreads();
    }
    if (tid == 0) thresh[b] = ((ull)V << 32) | (ull)s_prefix;
}

// ---------------- fused mask + column degree (vectorized) ------------------------
__global__ void deg_k(const float* __restrict__ x2, const ull* __restrict__ th,
                      float* __restrict__ dinv) {
    int b = blockIdx.x;
    int t = threadIdx.x;     // 128, first 100 active
    if (t >= 100) return;
    ull thr = th[b];
    const float* xb = x2 + (size_t)b * NSQ;
    int j0 = 4 * t;
    float acc[4] = {0.f, 0.f, 0.f, 0.f};
    for (int i = 0; i < NN; i++) {
        float4 v = *(const float4*)&xb[(size_t)i * NN + j0];
        float vv[4] = {v.x, v.y, v.z, v.w};
        #pragma unroll
        for (int e = 0; e < 4; e++) {
            unsigned r = (unsigned)(i * NN + j0 + e);
            float a = (make_key(vv[e], r) >= thr) ? vv[e] : 0.f;
            if (i == j0 + e && a == 0.f) a = 1.f;
            acc[e] += a;
        }
    }
    #pragma unroll
    for (int e = 0; e < 4; e++) {
        float dv = rsqrtf(acc[e]);
        if (isinf(dv)) dv = 0.f;
        dinv[b * NN + j0 + e] = dv;
    }
}

// ---------------- fused mask + An split + row means (vectorized) -----------------
__global__ void an_k(const float* __restrict__ x2, const ull* __restrict__ th,
                     const float* __restrict__ dinv,
                     bf16* __restrict__ anh, bf16* __restrict__ anl,
                     float* __restrict__ rs) {
    int i = blockIdx.x, b = blockIdx.y;
    int t = threadIdx.x;     // 128, first 100 active
    ull thr = th[b];
    const float* dv = dinv + b * NN;
    size_t roff = (size_t)b * NSQ + (size_t)i * NN;
    float acc = 0.f;
    if (t < 100) {
        int j0 = 4 * t;
        float di = dv[i];
        float4 v = *(const float4*)&x2[roff + j0];
        float4 dj = *(const float4*)&dv[j0];
        float vv[4] = {v.x, v.y, v.z, v.w};
        float dd[4] = {dj.x, dj.y, dj.z, dj.w};
        float w[4];
        #pragma unroll
        for (int e = 0; e < 4; e++) {
            unsigned r = (unsigned)(i * NN + j0 + e);
            float a = (make_key(vv[e], r) >= thr) ? vv[e] : 0.f;
            if (i == j0 + e && a == 0.f) a = 1.f;
            w[e] = a * di * dd[e];
            acc += w[e];
        }
        uint2 ph, pl;
        fsplit4(w, &ph, &pl);
        *(uint2*)&anh[roff + j0] = ph;
        *(uint2*)&anl[roff + j0] = pl;
    }
    __shared__ float sb[128];
    sb[t] = acc;
    __syncthreads();
    for (int s = 64; s > 0; s >>= 1) {
        if (t < s) sb[t] += sb[t + s];
        __syncthreads();
    }
    if (t == 0) rs[b * NN + i] = sb[0] * (1.f / NN);
}

// =============== cp.async double-buffered bf16 split GEMM =======================
#define BM 128
#define BN 64
#define BK 32
#define BKP 40
#define BNP 72
#define ABUF (BM * BKP * 2)
#define ASTG (2 * ABUF)
#define BBUF (BK * BNP * 2)
#define BSTG (2 * BBUF)
#define SMEM_TOT (2 * ASTG + 2 * BSTG)

__device__ __forceinline__ void ldm_x4(uint32_t* r, uint32_t a) {
    asm volatile("ldmatrix.sync.aligned.m8n8.x4.shared.b16 {%0,%1,%2,%3}, [%4];"
        : "=r"(r[0]), "=r"(r[1]), "=r"(r[2]), "=r"(r[3]) : "r"(a));
}
__device__ __forceinline__ void ldm_x2t(uint32_t* r, uint32_t a) {
    asm volatile("ldmatrix.sync.aligned.m8n8.x2.trans.shared.b16 {%0,%1}, [%2];"
        : "=r"(r[0]), "=r"(r[1]) : "r"(a));
}
__device__ __forceinline__ void mma16816(float* d, const uint32_t* a, const uint32_t* b) {
    asm volatile("mma.sync.aligned.m16n8k16.row.col.f32.bf16.bf16.f32 "
        "{%0,%1,%2,%3}, {%4,%5,%6,%7}, {%8,%9}, {%0,%1,%2,%3};"
        : "+f"(d[0]), "+f"(d[1]), "+f"(d[2]), "+f"(d[3])
        : "r"(a[0]), "r"(a[1]), "r"(a[2]), "r"(a[3]), "r"(b[0]), "r"(b[1]));
}
__device__ __forceinline__ void cpa16(uint32_t dst, const bf16* src, bool p) {
    int sz = p ? 16 : 0;
    asm volatile("cp.async.cg.shared.global [%0], [%1], 16, %2;"
        :: "r"(dst), "l"(src), "r"(sz));
}
__device__ __forceinline__ void cp_commit() {
    asm volatile("cp.async.commit_group;");
}
template<int W> __device__ __forceinline__ void cp_wait() {
    asm volatile("cp.async.wait_group %0;" :: "n"(W));
}

template<int EPI, int TRANSOUT, int OUTF>
__global__ void __launch_bounds__(256)
bgemm_k(const bf16* __restrict__ Ah, const bf16* __restrict__ Al, size_t sA, int lda,
        const bf16* __restrict__ Bh, const bf16* __restrict__ Bl, size_t sB, int ldb,
        const float* __restrict__ bias,
        const float* __restrict__ skip, size_t sS, int lds,
        float* __restrict__ Cf, bf16* __restrict__ Ch, bf16* __restrict__ Cl,
        size_t sC, int ldc, int M, int N, int K) {
    int bz = blockIdx.z;
    Ah += (size_t)bz * sA; Al += (size_t)bz * sA;
    Bh += (size_t)bz * sB; Bl += (size_t)bz * sB;
    if (EPI == 2) skip += (size_t)bz * sS;

    int n0 = blockIdx.x * BN;
    int m0 = blockIdx.y * BM;

    extern __shared__ bf16 dsm[];
    uint32_t smA = (uint32_t)__cvta_generic_to_shared(dsm);
    uint32_t smB = smA + 2 * ASTG;

    int tid = threadIdx.x;
    int warp = tid >> 5, lane = tid & 31;
    int wm = (warp >> 1) * 32;
    int wn = (warp & 1) * 32;
    int gid = lane >> 2, tig = lane & 3;

    const bf16* aSrc[4]; uint32_t aDst[4]; bool aPm[4]; int aC[4];
    #pragma unroll
    for (int it = 0; it < 4; it++) {
        int idx = tid + it * 256;
        int buf = idx >> 9;
        int rem = idx & 511;
        int r = rem >> 2, c = (rem & 3) * 8;
        int m = m0 + r;
        aPm[it] = m < M;
        aC[it] = c;
        aSrc[it] = (buf ? Al : Ah) + (size_t)(aPm[it] ? m : (M - 1)) * lda + c;
        aDst[it] = smA + buf * ABUF + (r * BKP + c) * 2;
    }
    const bf16* bSrc[2]; uint32_t bDst[2]; bool bPn[2]; int bR[2];
    #pragma unroll
    for (int it = 0; it < 2; it++) {
        int idx = tid + it * 256;
        int buf = idx >> 8;
        int rem = idx & 255;
        int r = rem >> 3, c = (rem & 7) * 8;
        bR[it] = r;
        bPn[it] = (n0 + c) < N;
        bSrc[it] = (buf ? Bl : Bh) + (size_t)r * ldb + (n0 + (bPn[it] ? c : 0));
        bDst[it] = smB + buf * BBUF + (r * BNP + c) * 2;
    }

    auto issue = [&](int k0, int stg) {
        #pragma unroll
        for (int it = 0; it < 4; it++)
            cpa16(aDst[it] + stg * ASTG, aSrc[it] + k0, aPm[it] && (k0 + aC[it] < K));
        #pragma unroll
        for (int it = 0; it < 2; it++)
            cpa16(bDst[it] + stg * BSTG, bSrc[it] + (size_t)k0 * ldb,
                  bPn[it] && (k0 + bR[it] < K));
        cp_commit();
    };

    float acc[2][4][4] = {};

    uint32_t aB0 = smA + ((wm + (lane & 15)) * BKP + (lane >> 4) * 8) * 2;
    uint32_t bB0 = smB + ((lane & 15) * BNP + wn) * 2;

    int nk = (K + BK - 1) / BK;
    issue(0, 0);
    for (int t = 0; t < nk; t++) {
        if (t + 1 < nk) { issue((t + 1) * BK, (t + 1) & 1); cp_wait<1>(); }
        else cp_wait<0>();
        __syncthreads();
        int stg = t & 1;
        uint32_t aH = aB0 + stg * ASTG;
        uint32_t aL = aH + ABUF;
        uint32_t bH = bB0 + stg * BSTG;
        uint32_t bL = bH + BBUF;
        #pragma unroll
        for (int kc = 0; kc < 2; kc++) {
            uint32_t ah[2][4], al[2][4];
            ldm_x4(ah[0], aH + kc * 32);
            ldm_x4(ah[1], aH + 16 * BKP * 2 + kc * 32);
            ldm_x4(al[0], aL + kc * 32);
            ldm_x4(al[1], aL + 16 * BKP * 2 + kc * 32);
            #pragma unroll
            for (int ni = 0; ni < 4; ni++) {
                uint32_t bh[2], bl[2];
                ldm_x2t(bh, bH + kc * 16 * BNP * 2 + ni * 16);
                ldm_x2t(bl, bL + kc * 16 * BNP * 2 + ni * 16);
                #pragma unroll
                for (int mi = 0; mi < 2; mi++) {
                    mma16816(acc[mi][ni], ah[mi], bh);
                    mma16816(acc[mi][ni], al[mi], bh);
                    mma16816(acc[mi][ni], ah[mi], bl);
                }
            }
        }
        __syncthreads();
    }

    #pragma unroll
    for (int mi = 0; mi < 2; mi++) {
        #pragma unroll
        for (int ni = 0; ni < 4; ni++) {
            int cbase = n0 + wn + ni * 8 + 2 * tig;
            #pragma unroll
            for (int h = 0; h < 2; h++) {
                int m = m0 + wm + mi * 16 + gid + h * 8;
                if (m >= M) continue;
                #pragma unroll
                for (int e = 0; e < 2; e++) {
                    int n = cbase + e;
                    if (n >= N) continue;
                    float v = acc[mi][ni][h * 2 + e];
                    if (EPI == 3) v += bias[m];
                    else if (bias) v += bias[n];
                    if (EPI == 2) v += skip[(size_t)m * lds + n];
                    if (EPI >= 1) v = fmaxf(v, 0.f);
                    size_t off = TRANSOUT ? ((size_t)n * ldc + m) : ((size_t)m * ldc + n);
                    if (OUTF & 1) Cf[(size_t)bz * sC + off] = v;
                    if (OUTF & 2) fsplit(v, &Ch[(size_t)bz * sC + off], &Cl[(size_t)bz * sC + off]);
                }
            }
        }
    }
}

// ---------------- head: warp-per-feature, coalesced ------------------------------
__global__ void head_k(const float* __restrict__ Y2T, const float* __restrict__ rs,
                       const float* __restrict__ b2, const float* __restrict__ fcw,
                       const float* __restrict__ fcb, float* __restrict__ out) {
    int b = blockIdx.x;
    int tid = threadIdx.x;     // 128
    int warp = tid >> 5, lane = tid & 31;
    __shared__ float sr[NN];
    __shared__ float sp[HH];
    const float* Yb = Y2T + (size_t)b * S_HN;
    const float* r = rs + b * NN;
    for (int i = tid; i < NN; i += 128) sr[i] = r[i];
    __syncthreads();
    for (int f = warp; f < HH; f += 4) {
        const float* Y = Yb + (size_t)f * NN;
        float acc = 0.f;
        for (int i = lane; i < NN; i += 32) acc += sr[i] * Y[i];
        #pragma unroll
        for (int o = 16; o > 0; o >>= 1) acc += __shfl_down_sync(0xffffffffu, acc, o);
        if (lane == 0) sp[f] = fmaxf(acc + b2[f], 0.f);
    }
    __syncthreads();
    if (tid < 2) {
        float o = fcb[tid];
        for (int q = 0; q < HH; q++) o += sp[q] * fcw[q * 2 + tid];
        out[b * 2 + tid] = o;
    }
}

// -----------------------------------------------------------------------------------
extern "C" void kernel_launch(void* const* d_in, const int* in_sizes, int n_in,
                              void* d_out, int out_size) {
    const float* x      = (const float*)d_in[0];
    const float* enc1_w = (const float*)d_in[2];
    const float* enc1_b = (const float*)d_in[3];
    const float* enc2_w = (const float*)d_in[4];
    const float* enc2_b = (const float*)d_in[5];
    const float* dec2_w = (const float*)d_in[6];
    const float* dec2_b = (const float*)d_in[7];
    const float* dec1_w = (const float*)d_in[8];
    const float* dec1_b = (const float*)d_in[9];
    const float* gcn1_w = (const float*)d_in[10];
    const float* gcn1_b = (const float*)d_in[11];
    const float* gcn2_w = (const float*)d_in[12];
    const float* gcn2_b = (const float*)d_in[13];
    const float* fc_w   = (const float*)d_in[14];
    const float* fc_b   = (const float*)d_in[15];
    float* out = (float*)d_out;

    float *xf, *delta, *out1, *y2t, *dinv, *rs;
    bf16 *ah, *al, *anh, *anl, *o1h, *o1l, *o2ah, *o2al, *o2th, *o2tl;
    bf16 *y1h, *y1l, *h1h, *h1l, *wh, *wl;
    ull* thresh;
    cudaGetSymbolAddress((void**)&xf, g_xf);
    cudaGetSymbolAddress((void**)&delta, g_delta);
    cudaGetSymbolAddress((void**)&out1, g_out1);
    cudaGetSymbolAddress((void**)&y2t, g_y2t);
    cudaGetSymbolAddress((void**)&ah, g_ah);
    cudaGetSymbolAddress((void**)&al, g_al);
    cudaGetSymbolAddress((void**)&anh, g_anh);
    cudaGetSymbolAddress((void**)&anl, g_anl);
    cudaGetSymbolAddress((void**)&o1h, g_o1h);
    cudaGetSymbolAddress((void**)&o1l, g_o1l);
    cudaGetSymbolAddress((void**)&o2ah, g_o2ah);
    cudaGetSymbolAddress((void**)&o2al, g_o2al);
    cudaGetSymbolAddress((void**)&o2th, g_o2th);
    cudaGetSymbolAddress((void**)&o2tl, g_o2tl);
    cudaGetSymbolAddress((void**)&y1h, g_y1h);
    cudaGetSymbolAddress((void**)&y1l, g_y1l);
    cudaGetSymbolAddress((void**)&h1h, g_h1h);
    cudaGetSymbolAddress((void**)&h1l, g_h1l);
    cudaGetSymbolAddress((void**)&wh, g_wh);
    cudaGetSymbolAddress((void**)&wl, g_wl);
    cudaGetSymbolAddress((void**)&thresh, g_thresh);
    cudaGetSymbolAddress((void**)&dinv, g_dinv);
    cudaGetSymbolAddress((void**)&rs, g_rs);

    cudaFuncSetAttribute((const void*)&bgemm_k<1,1,3>, cudaFuncAttributeMaxDynamicSharedMemorySize, SMEM_TOT);
    cudaFuncSetAttribute((const void*)&bgemm_k<1,0,2>, cudaFuncAttributeMaxDynamicSharedMemorySize, SMEM_TOT);
    cudaFuncSetAttribute((const void*)&bgemm_k<2,1,2>, cudaFuncAttributeMaxDynamicSharedMemorySize, SMEM_TOT);
    cudaFuncSetAttribute((const void*)&bgemm_k<0,0,1>, cudaFuncAttributeMaxDynamicSharedMemorySize, SMEM_TOT);
    cudaFuncSetAttribute((const void*)&bgemm_k<0,1,2>, cudaFuncAttributeMaxDynamicSharedMemorySize, SMEM_TOT);
    cudaFuncSetAttribute((const void*)&bgemm_k<3,0,2>, cudaFuncAttributeMaxDynamicSharedMemorySize, SMEM_TOT);

    // weight prep
    wsplit_k<<<200, 256>>>(enc1_w, wh + W_E1, wl + W_E1, 51200);
    wsplit_k<<<200, 256>>>(enc2_w, wh + W_E2, wl + W_E2, 51200);
    wsplit_k<<<200, 256>>>(dec2_w, wh + W_D2, wl + W_D2, 51200);
    wsplit_k<<<200, 256>>>(dec1_w, wh + W_D1, wl + W_D1, 51200);
    wsplit_k<<<200, 256>>>(gcn1_w, wh + W_G1, wl + W_G1, 51200);
    wtsplit_k<<<64, 256>>>(gcn2_w, wh + W_G2T, wl + W_G2T);

    // 0) fisher + split (vectorized)
    fisher_k<<<dim3(157, BATCH), 256>>>(x, xf, ah, al);

    // 1) out1 = relu(xf @ enc1_w + b) -> [H][N] fp32 + split
    bgemm_k<1, 1, 3><<<dim3(2, 4, BATCH), 256, SMEM_TOT>>>(
        ah, al, NSQ, NN, wh + W_E1, wl + W_E1, 0, HH, enc1_b,
        nullptr, 0, 0, out1, o1h, o1l, S_HN, NN, NN, HH, NN);

    // 2) out2a = relu(out1 @ enc2_w + b)
    bgemm_k<1, 0, 2><<<dim3(2, 1, BATCH), 256, SMEM_TOT>>>(
        o1h, o1l, S_HN, NN, wh + W_E2, wl + W_E2, 0, HH, enc2_b,
        nullptr, 0, 0, nullptr, o2ah, o2al, S_HH, HH, HH, HH, NN);

    // 3) out2 = relu(out2a @ dec2_w + b + out1) -> out2T [N][H] split
    bgemm_k<2, 1, 2><<<dim3(7, 1, BATCH), 256, SMEM_TOT>>>(
        o2ah, o2al, S_HH, HH, wh + W_D2, wl + W_D2, 0, NN, dec2_b,
        out1, S_HN, NN, nullptr, o2th, o2tl, S_HN, HH, HH, NN, HH);

    // 4) delta = out2T @ dec1_w + b  [400][400] fp32
    bgemm_k<0, 0, 1><<<dim3(7, 4, BATCH), 256, SMEM_TOT>>>(
        o2th, o2tl, S_HN, HH, wh + W_D1, wl + W_D1, 0, NN, dec1_b,
        nullptr, 0, 0, delta, nullptr, nullptr, NSQ, NN, NN, NN, HH);

    // 5) x2 = xf + 0.5*(delta+delta^T)*(1-eye), + split (symmetric pairs)
    sym2_k<<<dim3(91, BATCH), dim3(8, 32)>>>(xf, delta, ah, al);

    // 6) top-k threshold
    radix_select_k<<<BATCH, 512>>>(xf, thresh);

    // 7) fused mask + column degrees
    deg_k<<<BATCH, 128>>>(xf, thresh, dinv);

    // 8) fused mask + An split + row means
    an_k<<<dim3(NN, BATCH), 128>>>(xf, thresh, dinv, anh, anl, rs);

    // 9) Y1 = x2 @ gcn1_w -> Y1T [H][N] split
    bgemm_k<0, 1, 2><<<dim3(2, 4, BATCH), 256, SMEM_TOT>>>(
        ah, al, NSQ, NN, wh + W_G1, wl + W_G1, 0, HH, nullptr,
        nullptr, 0, 0, nullptr, y1h, y1l, S_HN, NN, NN, HH, NN);

    // 10) h1T = relu(Y1T @ An + gcn1_b[m])
    bgemm_k<3, 0, 2><<<dim3(7, 1, BATCH), 256, SMEM_TOT>>>(
        y1h, y1l, S_HN, NN, anh, anl, NSQ, NN, gcn1_b,
        nullptr, 0, 0, nullptr, h1h, h1l, S_HN, NN, HH, NN, NN);

    // 11) Y2T = gcn2_wT @ h1T  fp32
    bgemm_k<0, 0, 1><<<dim3(7, 1, BATCH), 256, SMEM_TOT>>>(
        wh + W_G2T, wl + W_G2T, 0, HH, h1h, h1l, S_HN, NN, nullptr,
        nullptr, 0, 0, y2t, nullptr, nullptr, S_HN, NN, HH, NN, HH);

    // 12) head
    head_k<<<BATCH, 128>>>(y2t, rs, gcn2_b, fc_w, fc_b, out);
}

// round 7
// speedup vs baseline: 3.8857x; 1.1248x over previous
#include <cuda_runtime.h>
#include <cuda_bf16.h>
#include <cstdint>

#define EPS 1e-9f
#define BATCH 128
#define NN 400
#define HH 128
#define NSQ (NN * NN)          // 160000
#define NQ4 (NSQ / 4)          // 40000
#define S_HN (HH * NN)         // 51200
#define S_HH (HH * HH)         // 16384
#define KTOP 32000

typedef __nv_bfloat16 bf16;
typedef unsigned long long ull;

// ---------------- scratch -----------------------------------------------------
__device__ float g_xf[BATCH * NSQ];
__device__ float g_delta[BATCH * NSQ];
__device__ float g_out1[BATCH * S_HN];
__device__ float g_y2t[BATCH * S_HN];
__device__ float g_degp[BATCH * 4 * NN];
__device__ bf16 g_ah[BATCH * NSQ], g_al[BATCH * NSQ];
__device__ bf16 g_anh[BATCH * NSQ], g_anl[BATCH * NSQ];
__device__ bf16 g_o1h[BATCH * S_HN], g_o1l[BATCH * S_HN];
__device__ bf16 g_o2ah[BATCH * S_HH], g_o2al[BATCH * S_HH];
__device__ bf16 g_o2th[BATCH * S_HN], g_o2tl[BATCH * S_HN];
__device__ bf16 g_y1h[BATCH * S_HN], g_y1l[BATCH * S_HN];
__device__ bf16 g_h1h[BATCH * S_HN], g_h1l[BATCH * S_HN];
__device__ bf16 g_wh[272384], g_wl[272384];
__device__ ull g_thresh[BATCH];
__device__ float g_dinv[BATCH * NN];
__device__ float g_rs[BATCH * NN];

#define W_E1 0
#define W_E2 51200
#define W_D2 102400
#define W_D1 153600
#define W_G1 204800
#define W_G2T 256000

__device__ __forceinline__ void fsplit(float v, bf16* h, bf16* l) {
    bf16 hh = __float2bfloat16(v);
    *h = hh;
    *l = __float2bfloat16(v - __bfloat162float(hh));
}
__device__ __forceinline__ void fsplit4(const float* v, uint2* ph, uint2* pl) {
    unsigned short h[4], l[4];
    #pragma unroll
    for (int e = 0; e < 4; e++) {
        bf16 hh = __float2bfloat16(v[e]);
        h[e] = __bfloat16_as_ushort(hh);
        l[e] = __bfloat16_as_ushort(__float2bfloat16(v[e] - __bfloat162float(hh)));
    }
    ph->x = (unsigned)h[0] | ((unsigned)h[1] << 16);
    ph->y = (unsigned)h[2] | ((unsigned)h[3] << 16);
    pl->x = (unsigned)l[0] | ((unsigned)l[1] << 16);
    pl->y = (unsigned)l[2] | ((unsigned)l[3] << 16);
}

// ---------------- weight prep --------------------------------------------------
__global__ void wsplit_k(const float* __restrict__ w, bf16* __restrict__ h,
                         bf16* __restrict__ l, int n) {
    int i = blockIdx.x * 256 + threadIdx.x;
    if (i < n) fsplit(w[i], &h[i], &l[i]);
}
__global__ void wtsplit_k(const float* __restrict__ w, bf16* __restrict__ h,
                          bf16* __restrict__ l) {
    int i = blockIdx.x * 256 + threadIdx.x;
    int g = i >> 7, f = i & 127;
    fsplit(w[f * HH + g], &h[i], &l[i]);
}

// ---------------- fisher + split ------------------------------------------------
__global__ void fisher_k(const float* __restrict__ x, float* __restrict__ xf,
                         bf16* __restrict__ xh, bf16* __restrict__ xl) {
    int t = blockIdx.x * 256 + threadIdx.x;
    int b = blockIdx.y;
    if (t >= NQ4) return;
    size_t base = (size_t)b * NSQ;
    float x00 = x[base];
    float d = 0.5f * __logf((1.f + x00 + EPS) / (1.f - x00 + EPS));
    float rd = 1.f / d;
    float4 v = ((const float4*)(x + base))[t];
    float o[4];
    o[0] = 0.5f * __logf((1.f + v.x + EPS) / (1.f - v.x + EPS)) * rd;
    o[1] = 0.5f * __logf((1.f + v.y + EPS) / (1.f - v.y + EPS)) * rd;
    o[2] = 0.5f * __logf((1.f + v.z + EPS) / (1.f - v.z + EPS)) * rd;
    o[3] = 0.5f * __logf((1.f + v.w + EPS) / (1.f - v.w + EPS)) * rd;
    ((float4*)(xf + base))[t] = make_float4(o[0], o[1], o[2], o[3]);
    uint2 ph, pl;
    fsplit4(o, &ph, &pl);
    ((uint2*)(xh + base))[t] = ph;
    ((uint2*)(xl + base))[t] = pl;
}

// ---------------- symmetric-pair symmetrize + split -----------------------------
__global__ void sym2_k(float* __restrict__ xf, const float* __restrict__ delta,
                       bf16* __restrict__ xh, bf16* __restrict__ xl) {
    int b = blockIdx.y;
    int p = blockIdx.x;
    int ti = 0, rem = p;
    while (rem >= 13 - ti) { rem -= 13 - ti; ti++; }
    int tj = ti + rem;
    int i0 = ti * 32, j0 = tj * 32;
    int tx = threadIdx.x, ty = threadIdx.y;
    __shared__ float shA[32][33];
    __shared__ float shB[32][33];
    size_t base = (size_t)b * NSQ;
    bool diag = (ti == tj);

    {
        int r = i0 + ty, c = j0 + tx * 4;
        float4 v = make_float4(0.f, 0.f, 0.f, 0.f);
        if (r < NN && c < NN) v = *(const float4*)&delta[base + (size_t)r * NN + c];
        shA[ty][tx * 4 + 0] = v.x; shA[ty][tx * 4 + 1] = v.y;
        shA[ty][tx * 4 + 2] = v.z; shA[ty][tx * 4 + 3] = v.w;
    }
    if (!diag) {
        int r = j0 + ty, c = i0 + tx * 4;
        float4 v = make_float4(0.f, 0.f, 0.f, 0.f);
        if (r < NN && c < NN) v = *(const float4*)&delta[base + (size_t)r * NN + c];
        shB[ty][tx * 4 + 0] = v.x; shB[ty][tx * 4 + 1] = v.y;
        shB[ty][tx * 4 + 2] = v.z; shB[ty][tx * 4 + 3] = v.w;
    }
    __syncthreads();

    {
        int r = i0 + ty, c0 = j0 + tx * 4;
        if (r < NN && c0 < NN) {
            size_t idx = base + (size_t)r * NN + c0;
            float4 xv = *(const float4*)&xf[idx];
            float o[4] = {xv.x, xv.y, xv.z, xv.w};
            #pragma unroll
            for (int e = 0; e < 4; e++) {
                int c = c0 + e;
                float dT = diag ? shA[tx * 4 + e][ty] : shB[tx * 4 + e][ty];
                if (r != c) o[e] += 0.5f * (shA[ty][tx * 4 + e] + dT);
            }
            *(float4*)&xf[idx] = make_float4(o[0], o[1], o[2], o[3]);
            uint2 ph, pl;
            fsplit4(o, &ph, &pl);
            *(uint2*)&xh[idx] = ph;
            *(uint2*)&xl[idx] = pl;
        }
    }
    if (!diag) {
        int r = j0 + ty, c0 = i0 + tx * 4;
        if (r < NN && c0 < NN) {
            size_t idx = base + (size_t)r * NN + c0;
            float4 xv = *(const float4*)&xf[idx];
            float o[4] = {xv.x, xv.y, xv.z, xv.w};
            #pragma unroll
            for (int e = 0; e < 4; e++) {
                int c = c0 + e;
                if (r != c) o[e] += 0.5f * (shB[ty][tx * 4 + e] + shA[tx * 4 + e][ty]);
            }
            *(float4*)&xf[idx] = make_float4(o[0], o[1], o[2], o[3]);
            uint2 ph, pl;
            fsplit4(o, &ph, &pl);
            *(uint2*)&xh[idx] = ph;
            *(uint2*)&xl[idx] = pl;
        }
    }
}

// ---------------- keys ------------------------------------------------------------
__device__ __forceinline__ unsigned make_vkey(float v) {
    unsigned u = __float_as_uint(v);
    return (u & 0x80000000u) ? ~u : (u | 0x80000000u);
}
__device__ __forceinline__ ull make_key(float v, unsigned t) {
    return ((ull)make_vkey(v) << 32) | (ull)(~t);
}

// ---------------- exact top-k: two 12-bit passes + candidate resolve -------------
// dyn smem: hist[2][4096] (32KB) + ull buf[2048] (16KB) = 49152 B
__global__ void radix_select_k(const float* __restrict__ x2,
                               ull* __restrict__ thresh) {
    const int b = blockIdx.x;
    const float4* xp4 = (const float4*)(x2 + (size_t)b * NSQ);
    extern __shared__ unsigned rsm[];
    unsigned* hist = rsm;                 // [2][4096]
    ull* buf = (ull*)(rsm + 8192);        // [2048]
    __shared__ unsigned chunk[512];
    __shared__ unsigned wsum[16];
    __shared__ unsigned s_bin, s_rem, s_cnt;
    int tid = threadIdx.x;                // 512
    int lane = tid & 31, wid = tid >> 5;
    int hsel = (wid & 1) * 4096;
    if (tid == 0) { s_rem = KTOP; s_cnt = 0; }

    unsigned b1 = 0;
    #pragma unroll
    for (int pass = 0; pass < 2; pass++) {
        // zero hist
        for (int i = tid; i < 8192; i += 512) hist[i] = 0;
        __syncthreads();
        // histogram
        for (int t = tid; t < 40448; t += 512) {
            bool inr = t < NQ4;
            float4 v = inr ? xp4[t] : make_float4(0.f, 0.f, 0.f, 0.f);
            float vv[4] = {v.x, v.y, v.z, v.w};
            #pragma unroll
            for (int e = 0; e < 4; e++) {
                unsigned vk = make_vkey(vv[e]);
                bool ok = inr && (pass == 0 || (vk >> 20) == b1);
                unsigned bin = (pass == 0) ? (vk >> 20) : ((vk >> 8) & 4095);
                unsigned active = __ballot_sync(0xffffffffu, ok);
                if (ok) {
                    unsigned peers = __match_any_sync(active, bin);
                    int leader = __ffs(peers) - 1;
                    if (lane == leader) atomicAdd(&hist[hsel + bin], __popc(peers));
                }
            }
        }
        __syncthreads();
        // descending chunk sums: thread t owns bins 4095-8t .. 4088-8t
        unsigned cs = 0;
        #pragma unroll
        for (int k = 0; k < 8; k++) {
            int bin = 4095 - 8 * tid - k;
            cs += hist[bin] + hist[4096 + bin];
        }
        chunk[tid] = cs;
        // block inclusive scan over chunk (in thread order = descending bins)
        unsigned v = cs;
        #pragma unroll
        for (int o = 1; o < 32; o <<= 1) {
            unsigned u = __shfl_up_sync(0xffffffffu, v, o);
            if (lane >= o) v += u;
        }
        if (lane == 31) wsum[wid] = v;
        __syncthreads();
        if (wid == 0 && lane < 16) {
            unsigned w = wsum[lane];
            #pragma unroll
            for (int o = 1; o < 16; o <<= 1) {
                unsigned u = __shfl_up_sync(0x0000ffffu, w, o);
                if (lane >= o) w += u;
            }
            wsum[lane] = w;
        }
        __syncthreads();
        unsigned incl = v + (wid ? wsum[wid - 1] : 0);
        unsigned excl = incl - cs;
        unsigned rem = s_rem;
        if (rem > excl && rem <= incl) {
            unsigned c = excl;
            #pragma unroll
            for (int k = 0; k < 8; k++) {
                int bin = 4095 - 8 * tid - k;
                unsigned bc = hist[bin] + hist[4096 + bin];
                if (rem <= c + bc) { s_bin = (unsigned)bin; s_rem = rem - c; break; }
                c += bc;
            }
        }
        __syncthreads();
        if (pass == 0) b1 = s_bin;
    }
    unsigned pref24 = (b1 << 12) | s_bin;
    unsigned remf = s_rem;

    // collect candidates with (vkey >> 8) == pref24, full 64-bit keys
    for (int t = tid; t < NQ4; t += 512) {
        float4 v = xp4[t];
        float vv[4] = {v.x, v.y, v.z, v.w};
        #pragma unroll
        for (int e = 0; e < 4; e++) {
            if ((make_vkey(vv[e]) >> 8) == pref24) {
                unsigned p = atomicAdd(&s_cnt, 1);
                if (p < 2048) buf[p] = make_key(vv[e], (unsigned)(t * 4 + e));
            }
        }
    }
    __syncthreads();
    unsigned n = min(s_cnt, 2048u);
    // rank resolution: the remf-th largest candidate is the threshold key
    for (int t = tid; t < (int)n; t += 512) {
        ull k = buf[t];
        unsigned c = 0;
        for (unsigned j = 0; j < n; j++) c += (buf[j] > k);
        if (c == remf - 1) thresh[b] = k;
    }
}

// ---------------- fused mask + partial column degrees ----------------------------
__global__ void degp_k(const float* __restrict__ x2, const ull* __restrict__ th,
                       float* __restrict__ part) {
    int q = blockIdx.x, b = blockIdx.y;
    int j = threadIdx.x;   // 512, first 400 active
    if (j >= NN) return;
    ull thr = th[b];
    const float* xb = x2 + (size_t)b * NSQ;
    float acc = 0.f;
    int i0 = q * 100;
    #pragma unroll 4
    for (int i = i0; i < i0 + 100; i++) {
        float v = xb[(size_t)i * NN + j];
        unsigned r = (unsigned)(i * NN + j);
        float a = (make_key(v, r) >= thr) ? v : 0.f;
        if (i == j && a == 0.f) a = 1.f;
        acc += a;
    }
    part[((size_t)b * 4 + q) * NN + j] = acc;
}
__global__ void dinv_k(const float* __restrict__ part, float* __restrict__ dinv) {
    int b = blockIdx.x;
    int j = threadIdx.x;
    if (j >= NN) return;
    size_t base = (size_t)b * 4 * NN;
    float s = part[base + j] + part[base + NN + j] + part[base + 2 * NN + j] + part[base + 3 * NN + j];
    float dv = rsqrtf(s);
    if (isinf(dv)) dv = 0.f;
    dinv[b * NN + j] = dv;
}

// ---------------- fused mask + An split + row means ------------------------------
__global__ void an_k(const float* __restrict__ x2, const ull* __restrict__ th,
                     const float* __restrict__ dinv,
                     bf16* __restrict__ anh, bf16* __restrict__ anl,
                     float* __restrict__ rs) {
    int i = blockIdx.x, b = blockIdx.y;
    int t = threadIdx.x;
    ull thr = th[b];
    const float* dv = dinv + b * NN;
    size_t roff = (size_t)b * NSQ + (size_t)i * NN;
    float acc = 0.f;
    if (t < 100) {
        int j0 = 4 * t;
        float di = dv[i];
        float4 v = *(const float4*)&x2[roff + j0];
        float4 dj = *(const float4*)&dv[j0];
        float vv[4] = {v.x, v.y, v.z, v.w};
        float dd[4] = {dj.x, dj.y, dj.z, dj.w};
        float w[4];
        #pragma unroll
        for (int e = 0; e < 4; e++) {
            unsigned r = (unsigned)(i * NN + j0 + e);
            float a = (make_key(vv[e], r) >= thr) ? vv[e] : 0.f;
            if (i == j0 + e && a == 0.f) a = 1.f;
            w[e] = a * di * dd[e];
            acc += w[e];
        }
        uint2 ph, pl;
        fsplit4(w, &ph, &pl);
        *(uint2*)&anh[roff + j0] = ph;
        *(uint2*)&anl[roff + j0] = pl;
    }
    __shared__ float sb[128];
    sb[t] = acc;
    __syncthreads();
    for (int s = 64; s > 0; s >>= 1) {
        if (t < s) sb[t] += sb[t + s];
        __syncthreads();
    }
    if (t == 0) rs[b * NN + i] = sb[0] * (1.f / NN);
}

// =============== cp.async double-buffered bf16 split GEMM =======================
#define BM 128
#define BN 64
#define BK 32
#define BKP 40
#define BNP 72
#define ABUF (BM * BKP * 2)
#define ASTG (2 * ABUF)
#define BBUF (BK * BNP * 2)
#define BSTG (2 * BBUF)
#define SMEM_TOT (2 * ASTG + 2 * BSTG)

__device__ __forceinline__ void ldm_x4(uint32_t* r, uint32_t a) {
    asm volatile("ldmatrix.sync.aligned.m8n8.x4.shared.b16 {%0,%1,%2,%3}, [%4];"
        : "=r"(r[0]), "=r"(r[1]), "=r"(r[2]), "=r"(r[3]) : "r"(a));
}
__device__ __forceinline__ void ldm_x2t(uint32_t* r, uint32_t a) {
    asm volatile("ldmatrix.sync.aligned.m8n8.x2.trans.shared.b16 {%0,%1}, [%2];"
        : "=r"(r[0]), "=r"(r[1]) : "r"(a));
}
__device__ __forceinline__ void mma16816(float* d, const uint32_t* a, const uint32_t* b) {
    asm volatile("mma.sync.aligned.m16n8k16.row.col.f32.bf16.bf16.f32 "
        "{%0,%1,%2,%3}, {%4,%5,%6,%7}, {%8,%9}, {%0,%1,%2,%3};"
        : "+f"(d[0]), "+f"(d[1]), "+f"(d[2]), "+f"(d[3])
        : "r"(a[0]), "r"(a[1]), "r"(a[2]), "r"(a[3]), "r"(b[0]), "r"(b[1]));
}
__device__ __forceinline__ void cpa16(uint32_t dst, const bf16* src, bool p) {
    int sz = p ? 16 : 0;
    asm volatile("cp.async.cg.shared.global [%0], [%1], 16, %2;"
        :: "r"(dst), "l"(src), "r"(sz));
}
__device__ __forceinline__ void cp_commit() {
    asm volatile("cp.async.commit_group;");
}
template<int W> __device__ __forceinline__ void cp_wait() {
    asm volatile("cp.async.wait_group %0;" :: "n"(W));
}

template<int EPI, int TRANSOUT, int OUTF>
__global__ void __launch_bounds__(256)
bgemm_k(const bf16* __restrict__ Ah, const bf16* __restrict__ Al, size_t sA, int lda,
        const bf16* __restrict__ Bh, const bf16* __restrict__ Bl, size_t sB, int ldb,
        const float* __restrict__ bias,
        const float* __restrict__ skip, size_t sS, int lds,
        float* __restrict__ Cf, bf16* __restrict__ Ch, bf16* __restrict__ Cl,
        size_t sC, int ldc, int M, int N, int K) {
    int bz = blockIdx.z;
    Ah += (size_t)bz * sA; Al += (size_t)bz * sA;
    Bh += (size_t)bz * sB; Bl += (size_t)bz * sB;
    if (EPI == 2) skip += (size_t)bz * sS;

    int n0 = blockIdx.x * BN;
    int m0 = blockIdx.y * BM;

    extern __shared__ bf16 dsm[];
    uint32_t smA = (uint32_t)__cvta_generic_to_shared(dsm);
    uint32_t smB = smA + 2 * ASTG;

    int tid = threadIdx.x;
    int warp = tid >> 5, lane = tid & 31;
    int wm = (warp >> 1) * 32;
    int wn = (warp & 1) * 32;
    int gid = lane >> 2, tig = lane & 3;

    const bf16* aSrc[4]; uint32_t aDst[4]; bool aPm[4]; int aC[4];
    #pragma unroll
    for (int it = 0; it < 4; it++) {
        int idx = tid + it * 256;
        int buf = idx >> 9;
        int rem = idx & 511;
        int r = rem >> 2, c = (rem & 3) * 8;
        int m = m0 + r;
        aPm[it] = m < M;
        aC[it] = c;
        aSrc[it] = (buf ? Al : Ah) + (size_t)(aPm[it] ? m : (M - 1)) * lda + c;
        aDst[it] = smA + buf * ABUF + (r * BKP + c) * 2;
    }
    const bf16* bSrc[2]; uint32_t bDst[2]; bool bPn[2]; int bR[2];
    #pragma unroll
    for (int it = 0; it < 2; it++) {
        int idx = tid + it * 256;
        int buf = idx >> 8;
        int rem = idx & 255;
        int r = rem >> 3, c = (rem & 7) * 8;
        bR[it] = r;
        bPn[it] = (n0 + c) < N;
        bSrc[it] = (buf ? Bl : Bh) + (size_t)r * ldb + (n0 + (bPn[it] ? c : 0));
        bDst[it] = smB + buf * BBUF + (r * BNP + c) * 2;
    }

    auto issue = [&](int k0, int stg) {
        #pragma unroll
        for (int it = 0; it < 4; it++)
            cpa16(aDst[it] + stg * ASTG, aSrc[it] + k0, aPm[it] && (k0 + aC[it] < K));
        #pragma unroll
        for (int it = 0; it < 2; it++)
            cpa16(bDst[it] + stg * BSTG, bSrc[it] + (size_t)k0 * ldb,
                  bPn[it] && (k0 + bR[it] < K));
        cp_commit();
    };

    float acc[2][4][4] = {};

    uint32_t aB0 = smA + ((wm + (lane & 15)) * BKP + (lane >> 4) * 8) * 2;
    uint32_t bB0 = smB + ((lane & 15) * BNP + wn) * 2;

    int nk = (K + BK - 1) / BK;
    issue(0, 0);
    for (int t = 0; t < nk; t++) {
        if (t + 1 < nk) { issue((t + 1) * BK, (t + 1) & 1); cp_wait<1>(); }
        else cp_wait<0>();
        __syncthreads();
        int stg = t & 1;
        uint32_t aH = aB0 + stg * ASTG;
        uint32_t aL = aH + ABUF;
        uint32_t bH = bB0 + stg * BSTG;
        uint32_t bL = bH + BBUF;
        #pragma unroll
        for (int kc = 0; kc < 2; kc++) {
            uint32_t ah[2][4], al[2][4];
            ldm_x4(ah[0], aH + kc * 32);
            ldm_x4(ah[1], aH + 16 * BKP * 2 + kc * 32);
            ldm_x4(al[0], aL + kc * 32);
            ldm_x4(al[1], aL + 16 * BKP * 2 + kc * 32);
            #pragma unroll
            for (int ni = 0; ni < 4; ni++) {
                uint32_t bh[2], bl[2];
                ldm_x2t(bh, bH + kc * 16 * BNP * 2 + ni * 16);
                ldm_x2t(bl, bL + kc * 16 * BNP * 2 + ni * 16);
                #pragma unroll
                for (int mi = 0; mi < 2; mi++) {
                    mma16816(acc[mi][ni], ah[mi], bh);
                    mma16816(acc[mi][ni], al[mi], bh);
                    mma16816(acc[mi][ni], ah[mi], bl);
                }
            }
        }
        __syncthreads();
    }

    #pragma unroll
    for (int mi = 0; mi < 2; mi++) {
        #pragma unroll
        for (int ni = 0; ni < 4; ni++) {
            int cbase = n0 + wn + ni * 8 + 2 * tig;
            #pragma unroll
            for (int h = 0; h < 2; h++) {
                int m = m0 + wm + mi * 16 + gid + h * 8;
                if (m >= M) continue;
                #pragma unroll
                for (int e = 0; e < 2; e++) {
                    int n = cbase + e;
                    if (n >= N) continue;
                    float v = acc[mi][ni][h * 2 + e];
                    if (EPI == 3) v += bias[m];
                    else if (bias) v += bias[n];
                    if (EPI == 2) v += skip[(size_t)m * lds + n];
                    if (EPI >= 1) v = fmaxf(v, 0.f);
                    size_t off = TRANSOUT ? ((size_t)n * ldc + m) : ((size_t)m * ldc + n);
                    if (OUTF & 1) Cf[(size_t)bz * sC + off] = v;
                    if (OUTF & 2) fsplit(v, &Ch[(size_t)bz * sC + off], &Cl[(size_t)bz * sC + off]);
                }
            }
        }
    }
}

// ---------------- head ------------------------------------------------------------
__global__ void head_k(const float* __restrict__ Y2T, const float* __restrict__ rs,
                       const float* __restrict__ b2, const float* __restrict__ fcw,
                       const float* __restrict__ fcb, float* __restrict__ out) {
    int b = blockIdx.x;
    int tid = threadIdx.x;
    int warp = tid >> 5, lane = tid & 31;
    __shared__ float sr[NN];
    __shared__ float sp[HH];
    const float* Yb = Y2T + (size_t)b * S_HN;
    const float* r = rs + b * NN;
    for (int i = tid; i < NN; i += 128) sr[i] = r[i];
    __syncthreads();
    for (int f = warp; f < HH; f += 4) {
        const float* Y = Yb + (size_t)f * NN;
        float acc = 0.f;
        for (int i = lane; i < NN; i += 32) acc += sr[i] * Y[i];
        #pragma unroll
        for (int o = 16; o > 0; o >>= 1) acc += __shfl_down_sync(0xffffffffu, acc, o);
        if (lane == 0) sp[f] = fmaxf(acc + b2[f], 0.f);
    }
    __syncthreads();
    if (tid < 2) {
        float o = fcb[tid];
        for (int q = 0; q < HH; q++) o += sp[q] * fcw[q * 2 + tid];
        out[b * 2 + tid] = o;
    }
}

// -----------------------------------------------------------------------------------
extern "C" void kernel_launch(void* const* d_in, const int* in_sizes, int n_in,
                              void* d_out, int out_size) {
    const float* x      = (const float*)d_in[0];
    const float* enc1_w = (const float*)d_in[2];
    const float* enc1_b = (const float*)d_in[3];
    const float* enc2_w = (const float*)d_in[4];
    const float* enc2_b = (const float*)d_in[5];
    const float* dec2_w = (const float*)d_in[6];
    const float* dec2_b = (const float*)d_in[7];
    const float* dec1_w = (const float*)d_in[8];
    const float* dec1_b = (const float*)d_in[9];
    const float* gcn1_w = (const float*)d_in[10];
    const float* gcn1_b = (const float*)d_in[11];
    const float* gcn2_w = (const float*)d_in[12];
    const float* gcn2_b = (const float*)d_in[13];
    const float* fc_w   = (const float*)d_in[14];
    const float* fc_b   = (const float*)d_in[15];
    float* out = (float*)d_out;

    float *xf, *delta, *out1, *y2t, *degp, *dinv, *rs;
    bf16 *ah, *al, *anh, *anl, *o1h, *o1l, *o2ah, *o2al, *o2th, *o2tl;
    bf16 *y1h, *y1l, *h1h, *h1l, *wh, *wl;
    ull* thresh;
    cudaGetSymbolAddress((void**)&xf, g_xf);
    cudaGetSymbolAddress((void**)&delta, g_delta);
    cudaGetSymbolAddress((void**)&out1, g_out1);
    cudaGetSymbolAddress((void**)&y2t, g_y2t);
    cudaGetSymbolAddress((void**)&degp, g_degp);
    cudaGetSymbolAddress((void**)&ah, g_ah);
    cudaGetSymbolAddress((void**)&al, g_al);
    cudaGetSymbolAddress((void**)&anh, g_anh);
    cudaGetSymbolAddress((void**)&anl, g_anl);
    cudaGetSymbolAddress((void**)&o1h, g_o1h);
    cudaGetSymbolAddress((void**)&o1l, g_o1l);
    cudaGetSymbolAddress((void**)&o2ah, g_o2ah);
    cudaGetSymbolAddress((void**)&o2al, g_o2al);
    cudaGetSymbolAddress((void**)&o2th, g_o2th);
    cudaGetSymbolAddress((void**)&o2tl, g_o2tl);
    cudaGetSymbolAddress((void**)&y1h, g_y1h);
    cudaGetSymbolAddress((void**)&y1l, g_y1l);
    cudaGetSymbolAddress((void**)&h1h, g_h1h);
    cudaGetSymbolAddress((void**)&h1l, g_h1l);
    cudaGetSymbolAddress((void**)&wh, g_wh);
    cudaGetSymbolAddress((void**)&wl, g_wl);
    cudaGetSymbolAddress((void**)&thresh, g_thresh);
    cudaGetSymbolAddress((void**)&dinv, g_dinv);
    cudaGetSymbolAddress((void**)&rs, g_rs);

    cudaFuncSetAttribute((const void*)&bgemm_k<1,1,3>, cudaFuncAttributeMaxDynamicSharedMemorySize, SMEM_TOT);
    cudaFuncSetAttribute((const void*)&bgemm_k<1,0,2>, cudaFuncAttributeMaxDynamicSharedMemorySize, SMEM_TOT);
    cudaFuncSetAttribute((const void*)&bgemm_k<2,1,2>, cudaFuncAttributeMaxDynamicSharedMemorySize, SMEM_TOT);
    cudaFuncSetAttribute((const void*)&bgemm_k<0,0,1>, cudaFuncAttributeMaxDynamicSharedMemorySize, SMEM_TOT);
    cudaFuncSetAttribute((const void*)&bgemm_k<0,1,2>, cudaFuncAttributeMaxDynamicSharedMemorySize, SMEM_TOT);
    cudaFuncSetAttribute((const void*)&bgemm_k<3,0,2>, cudaFuncAttributeMaxDynamicSharedMemorySize, SMEM_TOT);
    cudaFuncSetAttribute((const void*)&radix_select_k, cudaFuncAttributeMaxDynamicSharedMemorySize, 49152);

    // one-time side stream + fork/join events (host objects; identical GPU work
    // every call; standard multi-stream graph-capture fork pattern)
    static cudaStream_t s2 = nullptr;
    static cudaEvent_t evA = nullptr, evB = nullptr, evC = nullptr, evD = nullptr;
    if (!s2) {
        cudaStreamCreateWithFlags(&s2, cudaStreamNonBlocking);
        cudaEventCreateWithFlags(&evA, cudaEventDisableTiming);
        cudaEventCreateWithFlags(&evB, cudaEventDisableTiming);
        cudaEventCreateWithFlags(&evC, cudaEventDisableTiming);
        cudaEventCreateWithFlags(&evD, cudaEventDisableTiming);
    }

    // ---- fork 1: weight splits on s2, fisher on main ----
    cudaEventRecord(evA, 0);
    cudaStreamWaitEvent(s2, evA, 0);
    wsplit_k<<<200, 256, 0, s2>>>(enc1_w, wh + W_E1, wl + W_E1, 51200);
    wsplit_k<<<200, 256, 0, s2>>>(enc2_w, wh + W_E2, wl + W_E2, 51200);
    wsplit_k<<<200, 256, 0, s2>>>(dec2_w, wh + W_D2, wl + W_D2, 51200);
    wsplit_k<<<200, 256, 0, s2>>>(dec1_w, wh + W_D1, wl + W_D1, 51200);
    wsplit_k<<<200, 256, 0, s2>>>(gcn1_w, wh + W_G1, wl + W_G1, 51200);
    wtsplit_k<<<64, 256, 0, s2>>>(gcn2_w, wh + W_G2T, wl + W_G2T);
    cudaEventRecord(evB, s2);

    fisher_k<<<dim3(157, BATCH), 256>>>(x, xf, ah, al);
    cudaStreamWaitEvent(0, evB, 0);   // join before GEMM1

    // AE chain (main)
    bgemm_k<1, 1, 3><<<dim3(2, 4, BATCH), 256, SMEM_TOT>>>(
        ah, al, NSQ, NN, wh + W_E1, wl + W_E1, 0, HH, enc1_b,
        nullptr, 0, 0, out1, o1h, o1l, S_HN, NN, NN, HH, NN);
    bgemm_k<1, 0, 2><<<dim3(2, 1, BATCH), 256, SMEM_TOT>>>(
        o1h, o1l, S_HN, NN, wh + W_E2, wl + W_E2, 0, HH, enc2_b,
        nullptr, 0, 0, nullptr, o2ah, o2al, S_HH, HH, HH, HH, NN);
    bgemm_k<2, 1, 2><<<dim3(7, 1, BATCH), 256, SMEM_TOT>>>(
        o2ah, o2al, S_HH, HH, wh + W_D2, wl + W_D2, 0, NN, dec2_b,
        out1, S_HN, NN, nullptr, o2th, o2tl, S_HN, HH, HH, NN, HH);
    bgemm_k<0, 0, 1><<<dim3(7, 4, BATCH), 256, SMEM_TOT>>>(
        o2th, o2tl, S_HN, HH, wh + W_D1, wl + W_D1, 0, NN, dec1_b,
        nullptr, 0, 0, delta, nullptr, nullptr, NSQ, NN, NN, NN, HH);
    sym2_k<<<dim3(91, BATCH), dim3(8, 32)>>>(xf, delta, ah, al);

    // ---- fork 2: Y1 GEMM on s2, selection chain on main ----
    cudaEventRecord(evC, 0);
    cudaStreamWaitEvent(s2, evC, 0);
    bgemm_k<0, 1, 2><<<dim3(2, 4, BATCH), 256, SMEM_TOT, s2>>>(
        ah, al, NSQ, NN, wh + W_G1, wl + W_G1, 0, HH, nullptr,
        nullptr, 0, 0, nullptr, y1h, y1l, S_HN, NN, NN, HH, NN);
    cudaEventRecord(evD, s2);

    radix_select_k<<<BATCH, 512, 49152>>>(xf, thresh);
    degp_k<<<dim3(4, BATCH), 512>>>(xf, thresh, degp);
    dinv_k<<<BATCH, 512>>>(degp, dinv);
    an_k<<<dim3(NN, BATCH), 128>>>(xf, thresh, dinv, anh, anl, rs);

    cudaStreamWaitEvent(0, evD, 0);   // join before GCN aggregate

    bgemm_k<3, 0, 2><<<dim3(7, 1, BATCH), 256, SMEM_TOT>>>(
        y1h, y1l, S_HN, NN, anh, anl, NSQ, NN, gcn1_b,
        nullptr, 0, 0, nullptr, h1h, h1l, S_HN, NN, HH, NN, NN);
    bgemm_k<0, 0, 1><<<dim3(7, 1, BATCH), 256, SMEM_TOT>>>(
        wh + W_G2T, wl + W_G2T, 0, HH, h1h, h1l, S_HN, NN, nullptr,
        nullptr, 0, 0, y2t, nullptr, nullptr, S_HN, NN, HH, NN, HH);
    head_k<<<BATCH, 128>>>(y2t, rs, gcn2_b, fc_w, fc_b, out);
}